// round 12
// baseline (speedup 1.0000x reference)
#include <cuda_runtime.h>
#include <cstdint>
#include <cstddef>

#define N_NODES 10000
#define N_EDGES 160000
typedef unsigned long long ull;

// ---------------- scratch ----------------
__device__ float g_Y [N_NODES * 256];
__device__ float g_R [N_NODES * 256];
__device__ float g_H [N_NODES * 256];
__device__ float g_H2[N_NODES * 128];
__device__ float g_H3[N_NODES * 64];
__device__ float g_H4[N_NODES * 32];
__device__ float4 g_F [N_NODES];
__device__ int   g_cnt[N_NODES];
__device__ int   g_off[N_NODES + 1];
__device__ int   g_cur[N_NODES];
__device__ int   g_csr[N_EDGES];
__device__ int   g_is64;

// ---------------- CSR build ----------------
__global__ void init_kernel() {
    int i = blockIdx.x * blockDim.x + threadIdx.x;
    if (i < N_NODES) g_cnt[i] = 0;
    if (i == 0) g_is64 = 1;
}
__global__ void detect_kernel(const long long* __restrict__ ei) {
    int e = blockIdx.x * blockDim.x + threadIdx.x;
    if (e < N_EDGES) {
        long long v = ei[e];
        if (v < 0 || v >= N_NODES) g_is64 = 0;
    }
}
__device__ __forceinline__ void load_edge(const void* eiv, int e, int& s, int& d) {
    if (g_is64) {
        const long long* p = (const long long*)eiv;
        s = (int)p[e]; d = (int)p[N_EDGES + e];
    } else {
        const int* p = (const int*)eiv;
        s = p[e]; d = p[N_EDGES + e];
    }
}
__global__ void count_kernel(const void* __restrict__ eiv) {
    int e = blockIdx.x * blockDim.x + threadIdx.x;
    if (e < N_EDGES) { int s, d; load_edge(eiv, e, s, d); atomicAdd(&g_cnt[d], 1); }
}

__global__ void scan_kernel() {
    __shared__ int stage[10240];
    __shared__ int wsum[32];
    int t = threadIdx.x;
    int lane = t & 31, w = t >> 5;
#pragma unroll
    for (int i = 0; i < 10; i++) {
        int idx = t + i * 1024;
        stage[idx] = (idx < N_NODES) ? g_cnt[idx] : 0;
    }
    __syncthreads();
    int base = t * 10;
    int local[10];
    int s = 0;
#pragma unroll
    for (int i = 0; i < 10; i++) { local[i] = stage[base + i]; s += local[i]; }
    int v = s;
#pragma unroll
    for (int o = 1; o < 32; o <<= 1) {
        int u = __shfl_up_sync(0xFFFFFFFFu, v, o);
        if (lane >= o) v += u;
    }
    if (lane == 31) wsum[w] = v;
    __syncthreads();
    if (w == 0) {
        int x2 = wsum[lane];
#pragma unroll
        for (int o = 1; o < 32; o <<= 1) {
            int u = __shfl_up_sync(0xFFFFFFFFu, x2, o);
            if (lane >= o) x2 += u;
        }
        wsum[lane] = x2;
    }
    __syncthreads();
    int pre = v - s + (w > 0 ? wsum[w - 1] : 0);
#pragma unroll
    for (int i = 0; i < 10; i++) { stage[base + i] = pre; pre += local[i]; }
    if (t == 1023) g_off[N_NODES] = wsum[31];
    __syncthreads();
#pragma unroll
    for (int i = 0; i < 10; i++) {
        int idx = t + i * 1024;
        if (idx < N_NODES) {
            int p = stage[idx];
            g_off[idx] = p;
            g_cur[idx] = p;
        }
    }
}

__global__ void scatter_kernel(const void* __restrict__ eiv) {
    int e = blockIdx.x * blockDim.x + threadIdx.x;
    if (e < N_EDGES) {
        int s, d; load_edge(eiv, e, s, d);
        int p = atomicAdd(&g_cur[d], 1);
        g_csr[p] = s;
    }
}

// ---------------- big fused GEMM: FFMA2, 128x128 tile, plain-B + reg dup ----------------
// grid (4, 79): bx 0,1 -> Wl halves -> g_Y ; bx 2,3 -> Wr halves -> g_R.
// 256 thr = 8 warps, 2 blocks/SM. Warp w: rows bm0+16w..+15 (8 row-pairs);
// lane: col-pairs {2l,2l+1} and {2l+64,+65}.
__global__ __launch_bounds__(256, 2)
void sage_gemm5_kernel(const float* __restrict__ X,
                       const float* __restrict__ Wl, const float* __restrict__ Wr)
{
    constexpr int BK = 16, ASTRIDE = 136;
    __shared__ float AsT[BK][ASTRIDE];               // 128 rows used
    __shared__ __align__(16) float Bs[BK][128];

    int tid = threadIdx.x;
    int lane = tid & 31, wid = tid >> 5;
    int bx = blockIdx.x;
    int bm0 = blockIdx.y * 128;
    const float* B = (bx < 2) ? Wl : Wr;
    float* C = (bx < 2) ? g_Y : g_R;
    int bn0 = (bx & 1) * 128;

    // staging roles
    int rB = tid >> 5, cB = tid & 31;         // B: k-rows rB, rB+8; n-col-quad cB
    const float* pB0 = B + (size_t)rB * 256 + bn0 + cB * 4;
    const float* pB1 = B + (size_t)(rB + 8) * 256 + bn0 + cB * 4;

    ull acc2[8][4];
#pragma unroll
    for (int i = 0; i < 8; i++)
#pragma unroll
        for (int j = 0; j < 4; j++) acc2[i][j] = 0ull;

    for (int c = 0; c < 32; c++) {
        int k0 = c * BK;
        // A tile: 128 rows x 16 k, 2 float4 per thread, transposed store
#pragma unroll
        for (int l = 0; l < 2; l++) {
            int idx = tid + l * 256;
            int r = idx >> 2, q = idx & 3;
            int row = bm0 + r;
            float4 v = make_float4(0.f, 0.f, 0.f, 0.f);
            if (row < N_NODES) v = *(const float4*)(X + (size_t)row * 512 + k0 + q * 4);
            AsT[q * 4 + 0][r] = v.x;
            AsT[q * 4 + 1][r] = v.y;
            AsT[q * 4 + 2][r] = v.z;
            AsT[q * 4 + 3][r] = v.w;
        }
        // B tile plain
        float4 b0 = *(const float4*)(pB0 + (size_t)k0 * 256);
        float4 b1 = *(const float4*)(pB1 + (size_t)k0 * 256);
        *(float4*)&Bs[rB][cB * 4]     = b0;
        *(float4*)&Bs[rB + 8][cB * 4] = b1;
        __syncthreads();

#pragma unroll
        for (int k = 0; k < BK; k++) {
            const ulonglong2* ap = (const ulonglong2*)&AsT[k][wid * 16];
            ulonglong2 a01 = ap[0], a23 = ap[1], a45 = ap[2], a67 = ap[3];
            ull av[8] = { a01.x, a01.y, a23.x, a23.y, a45.x, a45.y, a67.x, a67.y };
            float2 f0 = *(const float2*)&Bs[k][2 * lane];
            float2 f1 = *(const float2*)&Bs[k][2 * lane + 64];
            ull b00, b01, b10, b11;
            asm("mov.b64 %0, {%1, %1};" : "=l"(b00) : "f"(f0.x));
            asm("mov.b64 %0, {%1, %1};" : "=l"(b01) : "f"(f0.y));
            asm("mov.b64 %0, {%1, %1};" : "=l"(b10) : "f"(f1.x));
            asm("mov.b64 %0, {%1, %1};" : "=l"(b11) : "f"(f1.y));
#pragma unroll
            for (int i = 0; i < 8; i++) {
                asm("fma.rn.f32x2 %0, %1, %2, %0;" : "+l"(acc2[i][0]) : "l"(av[i]), "l"(b00));
                asm("fma.rn.f32x2 %0, %1, %2, %0;" : "+l"(acc2[i][1]) : "l"(av[i]), "l"(b01));
                asm("fma.rn.f32x2 %0, %1, %2, %0;" : "+l"(acc2[i][2]) : "l"(av[i]), "l"(b10));
                asm("fma.rn.f32x2 %0, %1, %2, %0;" : "+l"(acc2[i][3]) : "l"(av[i]), "l"(b11));
            }
        }
        __syncthreads();
    }

#pragma unroll
    for (int i = 0; i < 8; i++) {
#pragma unroll
        for (int p = 0; p < 2; p++) {
            int row = bm0 + wid * 16 + 2 * i + p;
            if (row >= N_NODES) continue;
#pragma unroll
            for (int jj = 0; jj < 2; jj++) {
                int col = bn0 + 2 * lane + 64 * jj;
                ull u0 = acc2[i][2 * jj], u1 = acc2[i][2 * jj + 1];
                float v0 = __uint_as_float(p ? (unsigned)(u0 >> 32) : (unsigned)u0);
                float v1 = __uint_as_float(p ? (unsigned)(u1 >> 32) : (unsigned)u1);
                *(float2*)(C + (size_t)row * 256 + col) = make_float2(v0, v1);
            }
        }
    }
}

// ---------------- fp32 GEMM body (FFMA2, plain-B + reg dup) for MLP ----------------
template <int BN, int TN>
__device__ __forceinline__ void gemm_body(
    const float* __restrict__ A, const float* __restrict__ B,
    const float* __restrict__ bias, float* __restrict__ C,
    int M, int K, int Ncols, int relu, int bm0, int bn0)
{
    constexpr int BK = 16;
    constexpr int ASTRIDE = 136;
    constexpr int NJ = TN / 2;
    __shared__ float AsT[BK][ASTRIDE];
    __shared__ __align__(16) float Bs[BK][BN];

    int tid = threadIdx.x;
    int tx = tid & 15;
    int ty = tid >> 4;

    ull acc2[4][TN];
#pragma unroll
    for (int i = 0; i < 4; i++)
#pragma unroll
        for (int j = 0; j < TN; j++) acc2[i][j] = 0ull;

    for (int k0 = 0; k0 < K; k0 += BK) {
#pragma unroll
        for (int l = 0; l < 2; l++) {
            int idx = tid + l * 256;
            int r = idx >> 2, q = idx & 3;
            int row = bm0 + r;
            float4 v = make_float4(0.f, 0.f, 0.f, 0.f);
            if (row < M) v = *(const float4*)(A + (size_t)row * K + k0 + q * 4);
            AsT[q * 4 + 0][r] = v.x;
            AsT[q * 4 + 1][r] = v.y;
            AsT[q * 4 + 2][r] = v.z;
            AsT[q * 4 + 3][r] = v.w;
        }
#pragma unroll
        for (int idx = tid; idx < BK * BN; idx += 256) {
            int r = idx / BN, cc = idx % BN;
            Bs[r][cc] = B[(size_t)(k0 + r) * Ncols + bn0 + cc];
        }
        __syncthreads();

#pragma unroll
        for (int k = 0; k < BK; k++) {
            const ulonglong2* ap = (const ulonglong2*)&AsT[k][ty * 8];
            ulonglong2 a01 = ap[0];
            ulonglong2 a23 = ap[1];
            ull av[4] = { a01.x, a01.y, a23.x, a23.y };
#pragma unroll
            for (int jj = 0; jj < NJ; jj++) {
                float2 f = *(const float2*)&Bs[k][2 * tx + 32 * jj];
                ull bp0, bp1;
                asm("mov.b64 %0, {%1, %1};" : "=l"(bp0) : "f"(f.x));
                asm("mov.b64 %0, {%1, %1};" : "=l"(bp1) : "f"(f.y));
#pragma unroll
                for (int i = 0; i < 4; i++) {
                    asm("fma.rn.f32x2 %0, %1, %2, %0;"
                        : "+l"(acc2[i][2 * jj]) : "l"(av[i]), "l"(bp0));
                    asm("fma.rn.f32x2 %0, %1, %2, %0;"
                        : "+l"(acc2[i][2 * jj + 1]) : "l"(av[i]), "l"(bp1));
                }
            }
        }
        __syncthreads();
    }

#pragma unroll
    for (int i = 0; i < 4; i++) {
#pragma unroll
        for (int p = 0; p < 2; p++) {
            int row = bm0 + ty * 8 + 2 * i + p;
            if (row >= M) continue;
#pragma unroll
            for (int jj = 0; jj < NJ; jj++) {
                int col = bn0 + 2 * tx + 32 * jj;
                ull u0 = acc2[i][2 * jj], u1 = acc2[i][2 * jj + 1];
                float v0 = __uint_as_float(p ? (unsigned)(u0 >> 32) : (unsigned)u0);
                float v1 = __uint_as_float(p ? (unsigned)(u1 >> 32) : (unsigned)u1);
                if (bias) { v0 += bias[col]; v1 += bias[col + 1]; }
                if (relu) { v0 = fmaxf(v0, 0.f); v1 = fmaxf(v1, 0.f); }
                *(float2*)(C + (size_t)row * Ncols + col) = make_float2(v0, v1);
            }
        }
    }
}

template <int BN, int TN>
__global__ __launch_bounds__(256)
void gemm_kernel(const float* __restrict__ A, const float* __restrict__ B,
                 const float* __restrict__ bias, float* __restrict__ C,
                 int M, int K, int Ncols, int relu)
{
    gemm_body<BN, TN>(A, B, bias, C, M, K, Ncols, relu,
                      blockIdx.y * 128, blockIdx.x * BN);
}

// ---------------- aggregation ----------------
__global__ void aggr_kernel(const float* __restrict__ b_l) {
    int warp = (blockIdx.x * blockDim.x + threadIdx.x) >> 5;
    int lane = threadIdx.x & 31;
    if (warp >= N_NODES) return;
    int s0 = g_off[warp], s1 = g_off[warp + 1];

    float4 a0 = make_float4(0.f, 0.f, 0.f, 0.f);
    float4 a1 = a0;
    const float4* Y4 = (const float4*)g_Y;
    for (int e = s0; e < s1; e++) {
        int s = g_csr[e];
        float4 v0 = Y4[(size_t)s * 64 + lane];
        float4 v1 = Y4[(size_t)s * 64 + 32 + lane];
        a0.x += v0.x; a0.y += v0.y; a0.z += v0.z; a0.w += v0.w;
        a1.x += v1.x; a1.y += v1.y; a1.z += v1.z; a1.w += v1.w;
    }
    int deg = s1 - s0;
    float inv = (deg > 0) ? 1.0f / (float)deg : 1.0f;

    const float4* R4 = (const float4*)g_R;
    const float4* BL = (const float4*)b_l;
    float4* H4 = (float4*)g_H;

    float4 r0 = R4[(size_t)warp * 64 + lane];
    float4 r1 = R4[(size_t)warp * 64 + 32 + lane];
    float4 bl0 = BL[lane];
    float4 bl1 = BL[lane + 32];

    float4 o0, o1;
    o0.x = fmaxf(a0.x * inv + bl0.x + r0.x, 0.f);
    o0.y = fmaxf(a0.y * inv + bl0.y + r0.y, 0.f);
    o0.z = fmaxf(a0.z * inv + bl0.z + r0.z, 0.f);
    o0.w = fmaxf(a0.w * inv + bl0.w + r0.w, 0.f);
    o1.x = fmaxf(a1.x * inv + bl1.x + r1.x, 0.f);
    o1.y = fmaxf(a1.y * inv + bl1.y + r1.y, 0.f);
    o1.z = fmaxf(a1.z * inv + bl1.z + r1.z, 0.f);
    o1.w = fmaxf(a1.w * inv + bl1.w + r1.w, 0.f);
    H4[(size_t)warp * 64 + lane] = o0;
    H4[(size_t)warp * 64 + 32 + lane] = o1;
}

// ---------------- final layer ----------------
__global__ void final_kernel(const float* __restrict__ W3, const float* __restrict__ b3) {
    int n = blockIdx.x * blockDim.x + threadIdx.x;
    if (n >= N_NODES) return;
    float a0 = b3[0], a1 = b3[1], a2 = b3[2];
    const float* h = g_H4 + (size_t)n * 32;
#pragma unroll
    for (int k = 0; k < 32; k++) {
        float hv = h[k];
        a0 += hv * W3[k * 3 + 0];
        a1 += hv * W3[k * 3 + 1];
        a2 += hv * W3[k * 3 + 2];
    }
    g_F[n] = make_float4(a0, a1, a2, a0 * a0 + a1 * a1 + a2 * a2);
}

// ---------------- pairwise L2 ----------------
__device__ __forceinline__ float pdist(float4 a, float4 b) {
    float d2 = a.w + b.w - 2.0f * (a.x * b.x + a.y * b.y + a.z * b.z);
    if (d2 <= 0.f) return 0.f;
    float r;
    asm("sqrt.approx.f32 %0, %1;" : "=f"(r) : "f"(d2));
    return r;
}

__global__ __launch_bounds__(256)
void dist_kernel(float* __restrict__ out) {
    __shared__ float4 si[128], sj[128];
    int bi = blockIdx.y * 128, bj = blockIdx.x * 128;
    int t = threadIdx.x;
    if (t < 128) {
        int i = bi + t;
        si[t] = (i < N_NODES) ? g_F[i] : make_float4(0.f, 0.f, 0.f, 0.f);
    } else {
        int j = bj + t - 128;
        sj[t - 128] = (j < N_NODES) ? g_F[j] : make_float4(0.f, 0.f, 0.f, 0.f);
    }
    __syncthreads();

    int c4 = t & 31;
    int rb = t >> 5;
    int j0 = bj + c4 * 4;
    if (j0 >= N_NODES) return;

    float4 b0 = sj[c4 * 4 + 0];
    float4 b1 = sj[c4 * 4 + 1];
    float4 b2 = sj[c4 * 4 + 2];
    float4 b3 = sj[c4 * 4 + 3];

#pragma unroll 4
    for (int rr = 0; rr < 16; rr++) {
        int r = rb * 16 + rr;
        int i = bi + r;
        if (i >= N_NODES) break;
        float4 a = si[r];
        float4 o;
        o.x = pdist(a, b0);
        o.y = pdist(a, b1);
        o.z = pdist(a, b2);
        o.w = pdist(a, b3);
        *(float4*)(out + (size_t)i * N_NODES + j0) = o;
    }
}

// ---------------- launch ----------------
extern "C" void kernel_launch(void* const* d_in, const int* in_sizes, int n_in,
                              void* d_out, int out_size)
{
    const float* x   = (const float*)d_in[0];
    const void*  ei  = d_in[1];
    const float* W_l = (const float*)d_in[2];
    const float* b_l = (const float*)d_in[3];
    const float* W_r = (const float*)d_in[4];
    const float* Wa  = (const float*)d_in[5];
    const float* ba  = (const float*)d_in[6];
    const float* W1  = (const float*)d_in[7];
    const float* b1  = (const float*)d_in[8];
    const float* W2  = (const float*)d_in[9];
    const float* b2  = (const float*)d_in[10];
    const float* W3  = (const float*)d_in[11];
    const float* b3  = (const float*)d_in[12];
    float* out = (float*)d_out;

    float *pH, *pH2, *pH3, *pH4;
    cudaGetSymbolAddress((void**)&pH,  g_H);
    cudaGetSymbolAddress((void**)&pH2, g_H2);
    cudaGetSymbolAddress((void**)&pH3, g_H3);
    cudaGetSymbolAddress((void**)&pH4, g_H4);

    const int MBLK = (N_NODES + 127) / 128;   // 79

    init_kernel<<<(N_NODES + 255) / 256, 256>>>();
    detect_kernel<<<(N_EDGES + 255) / 256, 256>>>((const long long*)ei);
    count_kernel<<<(N_EDGES + 255) / 256, 256>>>(ei);

    // launch 3 (ncu slot): fused Y = x@W_l, R = x@W_r  (FFMA2, 128x128, plain-B)
    sage_gemm5_kernel<<<dim3(4, MBLK), 256>>>(x, W_l, W_r);

    scan_kernel<<<1, 1024>>>();
    scatter_kernel<<<(N_EDGES + 255) / 256, 256>>>(ei);

    aggr_kernel<<<(N_NODES * 32 + 255) / 256, 256>>>(b_l);

    gemm_kernel<128, 8><<<dim3(1, MBLK), 256>>>(pH,  Wa, ba, pH2, N_NODES, 256, 128, 1);
    gemm_kernel<64, 4><<<dim3(1, MBLK), 256>>>(pH2, W1, b1, pH3, N_NODES, 128, 64, 1);
    gemm_kernel<32, 2><<<dim3(1, MBLK), 256>>>(pH3, W2, b2, pH4, N_NODES, 64, 32, 1);
    final_kernel<<<(N_NODES + 255) / 256, 256>>>(W3, b3);

    dist_kernel<<<dim3(MBLK, MBLK), 256>>>(out);

    (void)in_sizes; (void)n_in; (void)out_size;
}

// round 13
// speedup vs baseline: 1.0769x; 1.0769x over previous
#include <cuda_runtime.h>
#include <cstdint>
#include <cstddef>

#define N_NODES 10000
#define N_EDGES 160000
typedef unsigned long long ull;

// ---------------- scratch ----------------
__device__ float g_Y [N_NODES * 256];
__device__ float g_R [N_NODES * 256];
__device__ float g_H [N_NODES * 256];
__device__ float g_H2[N_NODES * 128];
__device__ float g_H3[N_NODES * 64];
__device__ float g_H4[N_NODES * 32];
__device__ float4 g_F [N_NODES];
__device__ int   g_cnt[N_NODES];
__device__ int   g_off[N_NODES + 1];
__device__ int   g_cur[N_NODES];
__device__ int   g_csr[N_EDGES];
__device__ int   g_is64;

// ---------------- CSR build ----------------
__global__ void init_kernel() {
    int i = blockIdx.x * blockDim.x + threadIdx.x;
    if (i < N_NODES) g_cnt[i] = 0;
    if (i == 0) g_is64 = 1;
}
__global__ void detect_kernel(const long long* __restrict__ ei) {
    int e = blockIdx.x * blockDim.x + threadIdx.x;
    if (e < N_EDGES) {
        long long v = ei[e];
        if (v < 0 || v >= N_NODES) g_is64 = 0;
    }
}
__device__ __forceinline__ void load_edge(const void* eiv, int e, int& s, int& d) {
    if (g_is64) {
        const long long* p = (const long long*)eiv;
        s = (int)p[e]; d = (int)p[N_EDGES + e];
    } else {
        const int* p = (const int*)eiv;
        s = p[e]; d = p[N_EDGES + e];
    }
}
__global__ void count_kernel(const void* __restrict__ eiv) {
    int e = blockIdx.x * blockDim.x + threadIdx.x;
    if (e < N_EDGES) { int s, d; load_edge(eiv, e, s, d); atomicAdd(&g_cnt[d], 1); }
}

__global__ void scan_kernel() {
    __shared__ int stage[10240];
    __shared__ int wsum[32];
    int t = threadIdx.x;
    int lane = t & 31, w = t >> 5;
#pragma unroll
    for (int i = 0; i < 10; i++) {
        int idx = t + i * 1024;
        stage[idx] = (idx < N_NODES) ? g_cnt[idx] : 0;
    }
    __syncthreads();
    int base = t * 10;
    int local[10];
    int s = 0;
#pragma unroll
    for (int i = 0; i < 10; i++) { local[i] = stage[base + i]; s += local[i]; }
    int v = s;
#pragma unroll
    for (int o = 1; o < 32; o <<= 1) {
        int u = __shfl_up_sync(0xFFFFFFFFu, v, o);
        if (lane >= o) v += u;
    }
    if (lane == 31) wsum[w] = v;
    __syncthreads();
    if (w == 0) {
        int x2 = wsum[lane];
#pragma unroll
        for (int o = 1; o < 32; o <<= 1) {
            int u = __shfl_up_sync(0xFFFFFFFFu, x2, o);
            if (lane >= o) x2 += u;
        }
        wsum[lane] = x2;
    }
    __syncthreads();
    int pre = v - s + (w > 0 ? wsum[w - 1] : 0);
#pragma unroll
    for (int i = 0; i < 10; i++) { stage[base + i] = pre; pre += local[i]; }
    if (t == 1023) g_off[N_NODES] = wsum[31];
    __syncthreads();
#pragma unroll
    for (int i = 0; i < 10; i++) {
        int idx = t + i * 1024;
        if (idx < N_NODES) {
            int p = stage[idx];
            g_off[idx] = p;
            g_cur[idx] = p;
        }
    }
}

__global__ void scatter_kernel(const void* __restrict__ eiv) {
    int e = blockIdx.x * blockDim.x + threadIdx.x;
    if (e < N_EDGES) {
        int s, d; load_edge(eiv, e, s, d);
        int p = atomicAdd(&g_cur[d], 1);
        g_csr[p] = s;
    }
}

// ---------------- big fused GEMM: FFMA2, 64x128, plain-B + reg dup (R11 best) ----------------
__global__ __launch_bounds__(256, 3)
void sage_gemm4_kernel(const float* __restrict__ X,
                       const float* __restrict__ Wl, const float* __restrict__ Wr)
{
    constexpr int BK = 16, ASTRIDE = 72;
    __shared__ float AsT[BK][ASTRIDE];               // 64 rows used
    __shared__ __align__(16) float Bs[BK][128];

    int tid = threadIdx.x;
    int lane = tid & 31, wid = tid >> 5;
    int bx = blockIdx.x;
    int bm0 = blockIdx.y * 64;
    const float* B = (bx < 2) ? Wl : Wr;
    float* C = (bx < 2) ? g_Y : g_R;
    int bn0 = (bx & 1) * 128;

    int rA = tid >> 2, qA = tid & 3;
    int rB = tid >> 5, cB = tid & 31;
    int rowA = bm0 + rA;
    const float* pA = X + (size_t)rowA * 512 + qA * 4;
    const float* pB0 = B + (size_t)rB * 256 + bn0 + cB * 4;
    const float* pB1 = B + (size_t)(rB + 8) * 256 + bn0 + cB * 4;

    ull acc2[4][4];
#pragma unroll
    for (int i = 0; i < 4; i++)
#pragma unroll
        for (int j = 0; j < 4; j++) acc2[i][j] = 0ull;

    for (int c = 0; c < 32; c++) {
        int k0 = c * BK;
        float4 a = (rowA < N_NODES) ? *(const float4*)(pA + k0)
                                    : make_float4(0.f, 0.f, 0.f, 0.f);
        float4 b0 = *(const float4*)(pB0 + (size_t)k0 * 256);
        float4 b1 = *(const float4*)(pB1 + (size_t)k0 * 256);

        AsT[qA * 4 + 0][rA] = a.x;
        AsT[qA * 4 + 1][rA] = a.y;
        AsT[qA * 4 + 2][rA] = a.z;
        AsT[qA * 4 + 3][rA] = a.w;
        *(float4*)&Bs[rB][cB * 4]     = b0;
        *(float4*)&Bs[rB + 8][cB * 4] = b1;
        __syncthreads();

#pragma unroll
        for (int k = 0; k < BK; k++) {
            const ulonglong2* ap = (const ulonglong2*)&AsT[k][wid * 8];
            ulonglong2 a01 = ap[0], a23 = ap[1];
            ull av[4] = { a01.x, a01.y, a23.x, a23.y };
            float2 f0 = *(const float2*)&Bs[k][2 * lane];
            float2 f1 = *(const float2*)&Bs[k][2 * lane + 64];
            ull b00, b01, b10, b11;
            asm("mov.b64 %0, {%1, %1};" : "=l"(b00) : "f"(f0.x));
            asm("mov.b64 %0, {%1, %1};" : "=l"(b01) : "f"(f0.y));
            asm("mov.b64 %0, {%1, %1};" : "=l"(b10) : "f"(f1.x));
            asm("mov.b64 %0, {%1, %1};" : "=l"(b11) : "f"(f1.y));
#pragma unroll
            for (int i = 0; i < 4; i++) {
                asm("fma.rn.f32x2 %0, %1, %2, %0;" : "+l"(acc2[i][0]) : "l"(av[i]), "l"(b00));
                asm("fma.rn.f32x2 %0, %1, %2, %0;" : "+l"(acc2[i][1]) : "l"(av[i]), "l"(b01));
                asm("fma.rn.f32x2 %0, %1, %2, %0;" : "+l"(acc2[i][2]) : "l"(av[i]), "l"(b10));
                asm("fma.rn.f32x2 %0, %1, %2, %0;" : "+l"(acc2[i][3]) : "l"(av[i]), "l"(b11));
            }
        }
        __syncthreads();
    }

#pragma unroll
    for (int i = 0; i < 4; i++) {
#pragma unroll
        for (int p = 0; p < 2; p++) {
            int row = bm0 + wid * 8 + 2 * i + p;
            if (row >= N_NODES) continue;
#pragma unroll
            for (int jj = 0; jj < 2; jj++) {
                int col = bn0 + 2 * lane + 64 * jj;
                ull u0 = acc2[i][2 * jj], u1 = acc2[i][2 * jj + 1];
                float v0 = __uint_as_float(p ? (unsigned)(u0 >> 32) : (unsigned)u0);
                float v1 = __uint_as_float(p ? (unsigned)(u1 >> 32) : (unsigned)u1);
                *(float2*)(C + (size_t)row * 256 + col) = make_float2(v0, v1);
            }
        }
    }
}

// ---------------- MLP GEMM body: templated BM, plain-B + reg dup ----------------
// 256 threads; tx = 16 col groups; ty = 16 row groups of TM=BM/16 rows.
template <int BM, int BN, int TN>
__device__ __forceinline__ void gemm_body(
    const float* __restrict__ A, const float* __restrict__ B,
    const float* __restrict__ bias, float* __restrict__ C,
    int M, int K, int Ncols, int relu, int bm0, int bn0)
{
    constexpr int BK = 16;
    constexpr int ASTRIDE = (BM == 128) ? 136 : 72;
    constexpr int NJ = TN / 2;
    constexpr int TM = BM / 16;          // rows per thread (8 or 4)
    constexpr int RP = TM / 2;           // row-pairs
    __shared__ float AsT[BK][ASTRIDE];
    __shared__ __align__(16) float Bs[BK][BN];

    int tid = threadIdx.x;
    int tx = tid & 15;
    int ty = tid >> 4;

    ull acc2[RP][TN];
#pragma unroll
    for (int i = 0; i < RP; i++)
#pragma unroll
        for (int j = 0; j < TN; j++) acc2[i][j] = 0ull;

    for (int k0 = 0; k0 < K; k0 += BK) {
        // A tile: BM rows x 16 k -> transposed. BM*4 float4 loads over 256 threads.
#pragma unroll
        for (int l = 0; l < BM / 64; l++) {
            int idx = tid + l * 256;
            int r = idx >> 2, q = idx & 3;
            int row = bm0 + r;
            float4 v = make_float4(0.f, 0.f, 0.f, 0.f);
            if (row < M) v = *(const float4*)(A + (size_t)row * K + k0 + q * 4);
            AsT[q * 4 + 0][r] = v.x;
            AsT[q * 4 + 1][r] = v.y;
            AsT[q * 4 + 2][r] = v.z;
            AsT[q * 4 + 3][r] = v.w;
        }
#pragma unroll
        for (int idx = tid; idx < BK * BN; idx += 256) {
            int r = idx / BN, cc = idx % BN;
            Bs[r][cc] = B[(size_t)(k0 + r) * Ncols + bn0 + cc];
        }
        __syncthreads();

#pragma unroll
        for (int k = 0; k < BK; k++) {
            ull av[RP];
#pragma unroll
            for (int i = 0; i < RP; i++)
                av[i] = *(const ull*)&AsT[k][ty * TM + 2 * i];
#pragma unroll
            for (int jj = 0; jj < NJ; jj++) {
                float2 f = *(const float2*)&Bs[k][2 * tx + 32 * jj];
                ull bp0, bp1;
                asm("mov.b64 %0, {%1, %1};" : "=l"(bp0) : "f"(f.x));
                asm("mov.b64 %0, {%1, %1};" : "=l"(bp1) : "f"(f.y));
#pragma unroll
                for (int i = 0; i < RP; i++) {
                    asm("fma.rn.f32x2 %0, %1, %2, %0;"
                        : "+l"(acc2[i][2 * jj]) : "l"(av[i]), "l"(bp0));
                    asm("fma.rn.f32x2 %0, %1, %2, %0;"
                        : "+l"(acc2[i][2 * jj + 1]) : "l"(av[i]), "l"(bp1));
                }
            }
        }
        __syncthreads();
    }

#pragma unroll
    for (int i = 0; i < RP; i++) {
#pragma unroll
        for (int p = 0; p < 2; p++) {
            int row = bm0 + ty * TM + 2 * i + p;
            if (row >= M) continue;
#pragma unroll
            for (int jj = 0; jj < NJ; jj++) {
                int col = bn0 + 2 * tx + 32 * jj;
                ull u0 = acc2[i][2 * jj], u1 = acc2[i][2 * jj + 1];
                float v0 = __uint_as_float(p ? (unsigned)(u0 >> 32) : (unsigned)u0);
                float v1 = __uint_as_float(p ? (unsigned)(u1 >> 32) : (unsigned)u1);
                if (bias) { v0 += bias[col]; v1 += bias[col + 1]; }
                if (relu) { v0 = fmaxf(v0, 0.f); v1 = fmaxf(v1, 0.f); }
                *(float2*)(C + (size_t)row * Ncols + col) = make_float2(v0, v1);
            }
        }
    }
}

template <int BM, int BN, int TN>
__global__ __launch_bounds__(256)
void gemm_kernel(const float* __restrict__ A, const float* __restrict__ B,
                 const float* __restrict__ bias, float* __restrict__ C,
                 int M, int K, int Ncols, int relu)
{
    gemm_body<BM, BN, TN>(A, B, bias, C, M, K, Ncols, relu,
                          blockIdx.y * BM, blockIdx.x * BN);
}

// ---------------- aggregation ----------------
__global__ void aggr_kernel(const float* __restrict__ b_l) {
    int warp = (blockIdx.x * blockDim.x + threadIdx.x) >> 5;
    int lane = threadIdx.x & 31;
    if (warp >= N_NODES) return;
    int s0 = g_off[warp], s1 = g_off[warp + 1];

    float4 a0 = make_float4(0.f, 0.f, 0.f, 0.f);
    float4 a1 = a0;
    const float4* Y4 = (const float4*)g_Y;
    for (int e = s0; e < s1; e++) {
        int s = g_csr[e];
        float4 v0 = Y4[(size_t)s * 64 + lane];
        float4 v1 = Y4[(size_t)s * 64 + 32 + lane];
        a0.x += v0.x; a0.y += v0.y; a0.z += v0.z; a0.w += v0.w;
        a1.x += v1.x; a1.y += v1.y; a1.z += v1.z; a1.w += v1.w;
    }
    int deg = s1 - s0;
    float inv = (deg > 0) ? 1.0f / (float)deg : 1.0f;

    const float4* R4 = (const float4*)g_R;
    const float4* BL = (const float4*)b_l;
    float4* H4 = (float4*)g_H;

    float4 r0 = R4[(size_t)warp * 64 + lane];
    float4 r1 = R4[(size_t)warp * 64 + 32 + lane];
    float4 bl0 = BL[lane];
    float4 bl1 = BL[lane + 32];

    float4 o0, o1;
    o0.x = fmaxf(a0.x * inv + bl0.x + r0.x, 0.f);
    o0.y = fmaxf(a0.y * inv + bl0.y + r0.y, 0.f);
    o0.z = fmaxf(a0.z * inv + bl0.z + r0.z, 0.f);
    o0.w = fmaxf(a0.w * inv + bl0.w + r0.w, 0.f);
    o1.x = fmaxf(a1.x * inv + bl1.x + r1.x, 0.f);
    o1.y = fmaxf(a1.y * inv + bl1.y + r1.y, 0.f);
    o1.z = fmaxf(a1.z * inv + bl1.z + r1.z, 0.f);
    o1.w = fmaxf(a1.w * inv + bl1.w + r1.w, 0.f);
    H4[(size_t)warp * 64 + lane] = o0;
    H4[(size_t)warp * 64 + 32 + lane] = o1;
}

// ---------------- final layer ----------------
__global__ void final_kernel(const float* __restrict__ W3, const float* __restrict__ b3) {
    int n = blockIdx.x * blockDim.x + threadIdx.x;
    if (n >= N_NODES) return;
    float a0 = b3[0], a1 = b3[1], a2 = b3[2];
    const float* h = g_H4 + (size_t)n * 32;
#pragma unroll
    for (int k = 0; k < 32; k++) {
        float hv = h[k];
        a0 += hv * W3[k * 3 + 0];
        a1 += hv * W3[k * 3 + 1];
        a2 += hv * W3[k * 3 + 2];
    }
    g_F[n] = make_float4(a0, a1, a2, a0 * a0 + a1 * a1 + a2 * a2);
}

// ---------------- pairwise L2 ----------------
__device__ __forceinline__ float pdist(float4 a, float4 b) {
    float d2 = a.w + b.w - 2.0f * (a.x * b.x + a.y * b.y + a.z * b.z);
    if (d2 <= 0.f) return 0.f;
    float r;
    asm("sqrt.approx.f32 %0, %1;" : "=f"(r) : "f"(d2));
    return r;
}

__global__ __launch_bounds__(256)
void dist_kernel(float* __restrict__ out) {
    __shared__ float4 si[128], sj[128];
    int bi = blockIdx.y * 128, bj = blockIdx.x * 128;
    int t = threadIdx.x;
    if (t < 128) {
        int i = bi + t;
        si[t] = (i < N_NODES) ? g_F[i] : make_float4(0.f, 0.f, 0.f, 0.f);
    } else {
        int j = bj + t - 128;
        sj[t - 128] = (j < N_NODES) ? g_F[j] : make_float4(0.f, 0.f, 0.f, 0.f);
    }
    __syncthreads();

    int c4 = t & 31;
    int rb = t >> 5;
    int j0 = bj + c4 * 4;
    if (j0 >= N_NODES) return;

    float4 b0 = sj[c4 * 4 + 0];
    float4 b1 = sj[c4 * 4 + 1];
    float4 b2 = sj[c4 * 4 + 2];
    float4 b3 = sj[c4 * 4 + 3];

#pragma unroll 4
    for (int rr = 0; rr < 16; rr++) {
        int r = rb * 16 + rr;
        int i = bi + r;
        if (i >= N_NODES) break;
        float4 a = si[r];
        float4 o;
        o.x = pdist(a, b0);
        o.y = pdist(a, b1);
        o.z = pdist(a, b2);
        o.w = pdist(a, b3);
        *(float4*)(out + (size_t)i * N_NODES + j0) = o;
    }
}

// ---------------- launch ----------------
extern "C" void kernel_launch(void* const* d_in, const int* in_sizes, int n_in,
                              void* d_out, int out_size)
{
    const float* x   = (const float*)d_in[0];
    const void*  ei  = d_in[1];
    const float* W_l = (const float*)d_in[2];
    const float* b_l = (const float*)d_in[3];
    const float* W_r = (const float*)d_in[4];
    const float* Wa  = (const float*)d_in[5];
    const float* ba  = (const float*)d_in[6];
    const float* W1  = (const float*)d_in[7];
    const float* b1  = (const float*)d_in[8];
    const float* W2  = (const float*)d_in[9];
    const float* b2  = (const float*)d_in[10];
    const float* W3  = (const float*)d_in[11];
    const float* b3  = (const float*)d_in[12];
    float* out = (float*)d_out;

    float *pH, *pH2, *pH3, *pH4;
    cudaGetSymbolAddress((void**)&pH,  g_H);
    cudaGetSymbolAddress((void**)&pH2, g_H2);
    cudaGetSymbolAddress((void**)&pH3, g_H3);
    cudaGetSymbolAddress((void**)&pH4, g_H4);

    const int MBLK = (N_NODES + 127) / 128;   // 79
    const int MBLK64 = (N_NODES + 63) / 64;   // 157

    init_kernel<<<(N_NODES + 255) / 256, 256>>>();
    detect_kernel<<<(N_EDGES + 255) / 256, 256>>>((const long long*)ei);
    count_kernel<<<(N_EDGES + 255) / 256, 256>>>(ei);

    // launch 3 (ncu slot): fused Y = x@W_l, R = x@W_r  (R11 best config)
    sage_gemm4_kernel<<<dim3(4, MBLK64), 256>>>(x, W_l, W_r);

    scan_kernel<<<1, 1024>>>();
    scatter_kernel<<<(N_EDGES + 255) / 256, 256>>>(ei);

    aggr_kernel<<<(N_NODES * 32 + 255) / 256, 256>>>(b_l);

    // MLP with BM=64 tiles (157 blocks each)
    gemm_kernel<64, 128, 8><<<dim3(1, MBLK64), 256>>>(pH,  Wa, ba, pH2, N_NODES, 256, 128, 1);
    gemm_kernel<64, 64, 4><<<dim3(1, MBLK64), 256>>>(pH2, W1, b1, pH3, N_NODES, 128, 64, 1);
    gemm_kernel<64, 32, 2><<<dim3(1, MBLK64), 256>>>(pH3, W2, b2, pH4, N_NODES, 64, 32, 1);
    final_kernel<<<(N_NODES + 255) / 256, 256>>>(W3, b3);

    dist_kernel<<<dim3(MBLK, MBLK), 256>>>(out);

    (void)in_sizes; (void)n_in; (void)out_size;
}

// round 14
// speedup vs baseline: 1.2047x; 1.1187x over previous
#include <cuda_runtime.h>
#include <cstdint>
#include <cstddef>

#define N_NODES 10000
#define N_EDGES 160000
typedef unsigned long long ull;

// ---------------- scratch ----------------
__device__ float g_Y [N_NODES * 256];
__device__ float g_R [N_NODES * 256];
__device__ float g_H [N_NODES * 256];
__device__ float4 g_F [N_NODES];
__device__ int   g_cnt[N_NODES];          // zero-initialized by loader; re-zeroed in scan
__device__ int   g_off[N_NODES + 1];
__device__ int   g_cur[N_NODES];
__device__ int   g_csr[N_EDGES];

// ---------------- big fused GEMM + edge count band ----------------
// grid (5, 157). bx 0,1 -> Wl halves -> g_Y ; bx 2,3 -> Wr -> g_R ; bx 4 -> edge count.
// GEMM: 64x128 tile, FFMA2, plain-B smem + register dup (R11 best config).
__global__ __launch_bounds__(256, 3)
void sage_gemm4_kernel(const float* __restrict__ X,
                       const float* __restrict__ Wl, const float* __restrict__ Wr,
                       const int* __restrict__ ei)
{
    constexpr int BK = 16, ASTRIDE = 72;
    __shared__ float AsT[BK][ASTRIDE];
    __shared__ __align__(16) float Bs[BK][128];

    int tid = threadIdx.x;
    int bx = blockIdx.x;

    if (bx == 4) {   // edge-count band: 157*256 = 40192 threads over 160000 edges
        int e = blockIdx.y * 256 + tid;
        for (; e < N_EDGES; e += 40192)
            atomicAdd(&g_cnt[ei[N_EDGES + e]], 1);
        return;
    }

    int lane = tid & 31, wid = tid >> 5;
    int bm0 = blockIdx.y * 64;
    const float* B = (bx < 2) ? Wl : Wr;
    float* C = (bx < 2) ? g_Y : g_R;
    int bn0 = (bx & 1) * 128;

    int rA = tid >> 2, qA = tid & 3;
    int rB = tid >> 5, cB = tid & 31;
    int rowA = bm0 + rA;
    const float* pA = X + (size_t)rowA * 512 + qA * 4;
    const float* pB0 = B + (size_t)rB * 256 + bn0 + cB * 4;
    const float* pB1 = B + (size_t)(rB + 8) * 256 + bn0 + cB * 4;

    ull acc2[4][4];
#pragma unroll
    for (int i = 0; i < 4; i++)
#pragma unroll
        for (int j = 0; j < 4; j++) acc2[i][j] = 0ull;

    for (int c = 0; c < 32; c++) {
        int k0 = c * BK;
        float4 a = (rowA < N_NODES) ? *(const float4*)(pA + k0)
                                    : make_float4(0.f, 0.f, 0.f, 0.f);
        float4 b0 = *(const float4*)(pB0 + (size_t)k0 * 256);
        float4 b1 = *(const float4*)(pB1 + (size_t)k0 * 256);

        AsT[qA * 4 + 0][rA] = a.x;
        AsT[qA * 4 + 1][rA] = a.y;
        AsT[qA * 4 + 2][rA] = a.z;
        AsT[qA * 4 + 3][rA] = a.w;
        *(float4*)&Bs[rB][cB * 4]     = b0;
        *(float4*)&Bs[rB + 8][cB * 4] = b1;
        __syncthreads();

#pragma unroll
        for (int k = 0; k < BK; k++) {
            const ulonglong2* ap = (const ulonglong2*)&AsT[k][wid * 8];
            ulonglong2 a01 = ap[0], a23 = ap[1];
            ull av[4] = { a01.x, a01.y, a23.x, a23.y };
            float2 f0 = *(const float2*)&Bs[k][2 * lane];
            float2 f1 = *(const float2*)&Bs[k][2 * lane + 64];
            ull b00, b01, b10, b11;
            asm("mov.b64 %0, {%1, %1};" : "=l"(b00) : "f"(f0.x));
            asm("mov.b64 %0, {%1, %1};" : "=l"(b01) : "f"(f0.y));
            asm("mov.b64 %0, {%1, %1};" : "=l"(b10) : "f"(f1.x));
            asm("mov.b64 %0, {%1, %1};" : "=l"(b11) : "f"(f1.y));
#pragma unroll
            for (int i = 0; i < 4; i++) {
                asm("fma.rn.f32x2 %0, %1, %2, %0;" : "+l"(acc2[i][0]) : "l"(av[i]), "l"(b00));
                asm("fma.rn.f32x2 %0, %1, %2, %0;" : "+l"(acc2[i][1]) : "l"(av[i]), "l"(b01));
                asm("fma.rn.f32x2 %0, %1, %2, %0;" : "+l"(acc2[i][2]) : "l"(av[i]), "l"(b10));
                asm("fma.rn.f32x2 %0, %1, %2, %0;" : "+l"(acc2[i][3]) : "l"(av[i]), "l"(b11));
            }
        }
        __syncthreads();
    }

#pragma unroll
    for (int i = 0; i < 4; i++) {
#pragma unroll
        for (int p = 0; p < 2; p++) {
            int row = bm0 + wid * 8 + 2 * i + p;
            if (row >= N_NODES) continue;
#pragma unroll
            for (int jj = 0; jj < 2; jj++) {
                int col = bn0 + 2 * lane + 64 * jj;
                ull u0 = acc2[i][2 * jj], u1 = acc2[i][2 * jj + 1];
                float v0 = __uint_as_float(p ? (unsigned)(u0 >> 32) : (unsigned)u0);
                float v1 = __uint_as_float(p ? (unsigned)(u1 >> 32) : (unsigned)u1);
                *(float2*)(C + (size_t)row * 256 + col) = make_float2(v0, v1);
            }
        }
    }
}

// ---------------- scan (also re-zeroes g_cnt for next replay) ----------------
__global__ void scan_kernel() {
    __shared__ int stage[10240];
    __shared__ int wsum[32];
    int t = threadIdx.x;
    int lane = t & 31, w = t >> 5;
#pragma unroll
    for (int i = 0; i < 10; i++) {
        int idx = t + i * 1024;
        stage[idx] = (idx < N_NODES) ? g_cnt[idx] : 0;
    }
    __syncthreads();
    int base = t * 10;
    int local[10];
    int s = 0;
#pragma unroll
    for (int i = 0; i < 10; i++) { local[i] = stage[base + i]; s += local[i]; }
    int v = s;
#pragma unroll
    for (int o = 1; o < 32; o <<= 1) {
        int u = __shfl_up_sync(0xFFFFFFFFu, v, o);
        if (lane >= o) v += u;
    }
    if (lane == 31) wsum[w] = v;
    __syncthreads();
    if (w == 0) {
        int x2 = wsum[lane];
#pragma unroll
        for (int o = 1; o < 32; o <<= 1) {
            int u = __shfl_up_sync(0xFFFFFFFFu, x2, o);
            if (lane >= o) x2 += u;
        }
        wsum[lane] = x2;
    }
    __syncthreads();
    int pre = v - s + (w > 0 ? wsum[w - 1] : 0);
#pragma unroll
    for (int i = 0; i < 10; i++) { stage[base + i] = pre; pre += local[i]; }
    if (t == 1023) g_off[N_NODES] = wsum[31];
    __syncthreads();
#pragma unroll
    for (int i = 0; i < 10; i++) {
        int idx = t + i * 1024;
        if (idx < N_NODES) {
            int p = stage[idx];
            g_off[idx] = p;
            g_cur[idx] = p;
            g_cnt[idx] = 0;     // reset for next graph replay
        }
    }
}

__global__ void scatter_kernel(const int* __restrict__ ei) {
    int e = blockIdx.x * blockDim.x + threadIdx.x;
    if (e < N_EDGES) {
        int s = ei[e];
        int d = ei[N_EDGES + e];
        int p = atomicAdd(&g_cur[d], 1);
        g_csr[p] = s;
    }
}

// ---------------- aggregation ----------------
__global__ void aggr_kernel(const float* __restrict__ b_l) {
    int warp = (blockIdx.x * blockDim.x + threadIdx.x) >> 5;
    int lane = threadIdx.x & 31;
    if (warp >= N_NODES) return;
    int s0 = g_off[warp], s1 = g_off[warp + 1];

    float4 a0 = make_float4(0.f, 0.f, 0.f, 0.f);
    float4 a1 = a0;
    const float4* Y4 = (const float4*)g_Y;
    for (int e = s0; e < s1; e++) {
        int s = g_csr[e];
        float4 v0 = Y4[(size_t)s * 64 + lane];
        float4 v1 = Y4[(size_t)s * 64 + 32 + lane];
        a0.x += v0.x; a0.y += v0.y; a0.z += v0.z; a0.w += v0.w;
        a1.x += v1.x; a1.y += v1.y; a1.z += v1.z; a1.w += v1.w;
    }
    int deg = s1 - s0;
    float inv = (deg > 0) ? 1.0f / (float)deg : 1.0f;

    const float4* R4 = (const float4*)g_R;
    const float4* BL = (const float4*)b_l;
    float4* H4 = (float4*)g_H;

    float4 r0 = R4[(size_t)warp * 64 + lane];
    float4 r1 = R4[(size_t)warp * 64 + 32 + lane];
    float4 bl0 = BL[lane];
    float4 bl1 = BL[lane + 32];

    float4 o0, o1;
    o0.x = fmaxf(a0.x * inv + bl0.x + r0.x, 0.f);
    o0.y = fmaxf(a0.y * inv + bl0.y + r0.y, 0.f);
    o0.z = fmaxf(a0.z * inv + bl0.z + r0.z, 0.f);
    o0.w = fmaxf(a0.w * inv + bl0.w + r0.w, 0.f);
    o1.x = fmaxf(a1.x * inv + bl1.x + r1.x, 0.f);
    o1.y = fmaxf(a1.y * inv + bl1.y + r1.y, 0.f);
    o1.z = fmaxf(a1.z * inv + bl1.z + r1.z, 0.f);
    o1.w = fmaxf(a1.w * inv + bl1.w + r1.w, 0.f);
    H4[(size_t)warp * 64 + lane] = o0;
    H4[(size_t)warp * 64 + 32 + lane] = o1;
}

// ---------------- fused MLP (256->128->64->32->3) + pairwise features ----------------
// One block = 64 rows, carries all layers in smem. Transposed tiles [col][row],
// column stride 66 (even -> ull-aligned A reads, <=2-way store conflicts).
#define S2 66
#define SA 68
#define MLP_SMEM ((128 * S2 + 64 * S2 + 32 * S2 + 2048 + 16 * SA) * 4)

__global__ __launch_bounds__(256)
void mlp_kernel(const float* __restrict__ Wa, const float* __restrict__ ba,
                const float* __restrict__ W1, const float* __restrict__ b1,
                const float* __restrict__ W2, const float* __restrict__ b2,
                const float* __restrict__ W3, const float* __restrict__ b3)
{
    extern __shared__ __align__(16) float sm[];
    float* H2s = sm;                       // [128][S2]
    float* H3s = H2s + 128 * S2;           // [64][S2]
    float* H4s = H3s + 64 * S2;            // [32][S2]
    float* Ws  = H4s + 32 * S2;            // up to 16*128
    float* Ast = Ws + 2048;                // [16][SA]

    int tid = threadIdx.x;
    int tx = tid & 15, ty = tid >> 4;
    int bm0 = blockIdx.x * 64;

    // ---- layer 1: g_H(64x256) @ Wa(256x128) + ba, relu -> H2s
    {
        ull acc[2][8];
#pragma unroll
        for (int i = 0; i < 2; i++)
#pragma unroll
            for (int j = 0; j < 8; j++) acc[i][j] = 0ull;

        int r = tid >> 2, q = tid & 3;
        int row = bm0 + r;
        for (int k0 = 0; k0 < 256; k0 += 16) {
            float4 v = make_float4(0.f, 0.f, 0.f, 0.f);
            if (row < N_NODES) v = *(const float4*)(g_H + (size_t)row * 256 + k0 + q * 4);
            Ast[(q * 4 + 0) * SA + r] = v.x;
            Ast[(q * 4 + 1) * SA + r] = v.y;
            Ast[(q * 4 + 2) * SA + r] = v.z;
            Ast[(q * 4 + 3) * SA + r] = v.w;
#pragma unroll
            for (int idx = tid; idx < 2048; idx += 256) {
                int rr = idx >> 7, cc = idx & 127;
                Ws[idx] = Wa[(size_t)(k0 + rr) * 128 + cc];
            }
            __syncthreads();
#pragma unroll
            for (int k = 0; k < 16; k++) {
                ull av0 = *(const ull*)&Ast[k * SA + ty * 4];
                ull av1 = *(const ull*)&Ast[k * SA + ty * 4 + 2];
#pragma unroll
                for (int j = 0; j < 4; j++) {
                    float2 f = *(const float2*)&Ws[k * 128 + 2 * tx + 32 * j];
                    ull bp0, bp1;
                    asm("mov.b64 %0, {%1, %1};" : "=l"(bp0) : "f"(f.x));
                    asm("mov.b64 %0, {%1, %1};" : "=l"(bp1) : "f"(f.y));
                    asm("fma.rn.f32x2 %0, %1, %2, %0;" : "+l"(acc[0][2 * j])     : "l"(av0), "l"(bp0));
                    asm("fma.rn.f32x2 %0, %1, %2, %0;" : "+l"(acc[1][2 * j])     : "l"(av1), "l"(bp0));
                    asm("fma.rn.f32x2 %0, %1, %2, %0;" : "+l"(acc[0][2 * j + 1]) : "l"(av0), "l"(bp1));
                    asm("fma.rn.f32x2 %0, %1, %2, %0;" : "+l"(acc[1][2 * j + 1]) : "l"(av1), "l"(bp1));
                }
            }
            __syncthreads();
        }
#pragma unroll
        for (int i = 0; i < 2; i++)
#pragma unroll
            for (int p = 0; p < 2; p++) {
                int rl = ty * 4 + 2 * i + p;
#pragma unroll
                for (int j = 0; j < 4; j++) {
                    int col = 2 * tx + 32 * j;
                    ull u0 = acc[i][2 * j], u1 = acc[i][2 * j + 1];
                    float v0 = __uint_as_float(p ? (unsigned)(u0 >> 32) : (unsigned)u0) + ba[col];
                    float v1 = __uint_as_float(p ? (unsigned)(u1 >> 32) : (unsigned)u1) + ba[col + 1];
                    H2s[col * S2 + rl]       = fmaxf(v0, 0.f);
                    H2s[(col + 1) * S2 + rl] = fmaxf(v1, 0.f);
                }
            }
        __syncthreads();
    }

    // ---- layer 2: H2s(64x128) @ W1(128x64) + b1, relu -> H3s
    {
        ull acc[2][4];
#pragma unroll
        for (int i = 0; i < 2; i++)
#pragma unroll
            for (int j = 0; j < 4; j++) acc[i][j] = 0ull;

        for (int k0 = 0; k0 < 128; k0 += 16) {
#pragma unroll
            for (int idx = tid; idx < 1024; idx += 256) {
                int rr = idx >> 6, cc = idx & 63;
                Ws[idx] = W1[(size_t)(k0 + rr) * 64 + cc];
            }
            __syncthreads();
#pragma unroll
            for (int k = 0; k < 16; k++) {
                ull av0 = *(const ull*)&H2s[(k0 + k) * S2 + ty * 4];
                ull av1 = *(const ull*)&H2s[(k0 + k) * S2 + ty * 4 + 2];
#pragma unroll
                for (int j = 0; j < 2; j++) {
                    float2 f = *(const float2*)&Ws[k * 64 + 2 * tx + 32 * j];
                    ull bp0, bp1;
                    asm("mov.b64 %0, {%1, %1};" : "=l"(bp0) : "f"(f.x));
                    asm("mov.b64 %0, {%1, %1};" : "=l"(bp1) : "f"(f.y));
                    asm("fma.rn.f32x2 %0, %1, %2, %0;" : "+l"(acc[0][2 * j])     : "l"(av0), "l"(bp0));
                    asm("fma.rn.f32x2 %0, %1, %2, %0;" : "+l"(acc[1][2 * j])     : "l"(av1), "l"(bp0));
                    asm("fma.rn.f32x2 %0, %1, %2, %0;" : "+l"(acc[0][2 * j + 1]) : "l"(av0), "l"(bp1));
                    asm("fma.rn.f32x2 %0, %1, %2, %0;" : "+l"(acc[1][2 * j + 1]) : "l"(av1), "l"(bp1));
                }
            }
            __syncthreads();
        }
#pragma unroll
        for (int i = 0; i < 2; i++)
#pragma unroll
            for (int p = 0; p < 2; p++) {
                int rl = ty * 4 + 2 * i + p;
#pragma unroll
                for (int j = 0; j < 2; j++) {
                    int col = 2 * tx + 32 * j;
                    ull u0 = acc[i][2 * j], u1 = acc[i][2 * j + 1];
                    float v0 = __uint_as_float(p ? (unsigned)(u0 >> 32) : (unsigned)u0) + b1[col];
                    float v1 = __uint_as_float(p ? (unsigned)(u1 >> 32) : (unsigned)u1) + b1[col + 1];
                    H3s[col * S2 + rl]       = fmaxf(v0, 0.f);
                    H3s[(col + 1) * S2 + rl] = fmaxf(v1, 0.f);
                }
            }
        __syncthreads();
    }

    // ---- layer 3: H3s(64x64) @ W2(64x32) + b2, relu -> H4s
    {
        ull acc[2][2];
#pragma unroll
        for (int i = 0; i < 2; i++)
#pragma unroll
            for (int j = 0; j < 2; j++) acc[i][j] = 0ull;

        for (int k0 = 0; k0 < 64; k0 += 16) {
#pragma unroll
            for (int idx = tid; idx < 512; idx += 256) {
                int rr = idx >> 5, cc = idx & 31;
                Ws[idx] = W2[(size_t)(k0 + rr) * 32 + cc];
            }
            __syncthreads();
#pragma unroll
            for (int k = 0; k < 16; k++) {
                ull av0 = *(const ull*)&H3s[(k0 + k) * S2 + ty * 4];
                ull av1 = *(const ull*)&H3s[(k0 + k) * S2 + ty * 4 + 2];
                float2 f = *(const float2*)&Ws[k * 32 + 2 * tx];
                ull bp0, bp1;
                asm("mov.b64 %0, {%1, %1};" : "=l"(bp0) : "f"(f.x));
                asm("mov.b64 %0, {%1, %1};" : "=l"(bp1) : "f"(f.y));
                asm("fma.rn.f32x2 %0, %1, %2, %0;" : "+l"(acc[0][0]) : "l"(av0), "l"(bp0));
                asm("fma.rn.f32x2 %0, %1, %2, %0;" : "+l"(acc[1][0]) : "l"(av1), "l"(bp0));
                asm("fma.rn.f32x2 %0, %1, %2, %0;" : "+l"(acc[0][1]) : "l"(av0), "l"(bp1));
                asm("fma.rn.f32x2 %0, %1, %2, %0;" : "+l"(acc[1][1]) : "l"(av1), "l"(bp1));
            }
            __syncthreads();
        }
#pragma unroll
        for (int i = 0; i < 2; i++)
#pragma unroll
            for (int p = 0; p < 2; p++) {
                int rl = ty * 4 + 2 * i + p;
                int col = 2 * tx;
                ull u0 = acc[i][0], u1 = acc[i][1];
                float v0 = __uint_as_float(p ? (unsigned)(u0 >> 32) : (unsigned)u0) + b2[col];
                float v1 = __uint_as_float(p ? (unsigned)(u1 >> 32) : (unsigned)u1) + b2[col + 1];
                H4s[col * S2 + rl]       = fmaxf(v0, 0.f);
                H4s[(col + 1) * S2 + rl] = fmaxf(v1, 0.f);
            }
        __syncthreads();
    }

    // ---- final: F = H4 @ W3 + b3, plus squared norm
    if (tid < 64) {
        int grow = bm0 + tid;
        if (grow < N_NODES) {
            float a0 = b3[0], a1 = b3[1], a2 = b3[2];
#pragma unroll
            for (int k = 0; k < 32; k++) {
                float hv = H4s[k * S2 + tid];
                a0 += hv * W3[k * 3 + 0];
                a1 += hv * W3[k * 3 + 1];
                a2 += hv * W3[k * 3 + 2];
            }
            g_F[grow] = make_float4(a0, a1, a2, a0 * a0 + a1 * a1 + a2 * a2);
        }
    }
}

// ---------------- pairwise L2 ----------------
__device__ __forceinline__ float pdist(float4 a, float4 b) {
    float d2 = a.w + b.w - 2.0f * (a.x * b.x + a.y * b.y + a.z * b.z);
    if (d2 <= 0.f) return 0.f;
    float r;
    asm("sqrt.approx.f32 %0, %1;" : "=f"(r) : "f"(d2));
    return r;
}

__global__ __launch_bounds__(256)
void dist_kernel(float* __restrict__ out) {
    __shared__ float4 si[128], sj[128];
    int bi = blockIdx.y * 128, bj = blockIdx.x * 128;
    int t = threadIdx.x;
    if (t < 128) {
        int i = bi + t;
        si[t] = (i < N_NODES) ? g_F[i] : make_float4(0.f, 0.f, 0.f, 0.f);
    } else {
        int j = bj + t - 128;
        sj[t - 128] = (j < N_NODES) ? g_F[j] : make_float4(0.f, 0.f, 0.f, 0.f);
    }
    __syncthreads();

    int c4 = t & 31;
    int rb = t >> 5;
    int j0 = bj + c4 * 4;
    if (j0 >= N_NODES) return;

    float4 b0 = sj[c4 * 4 + 0];
    float4 b1 = sj[c4 * 4 + 1];
    float4 b2 = sj[c4 * 4 + 2];
    float4 b3 = sj[c4 * 4 + 3];

#pragma unroll 4
    for (int rr = 0; rr < 16; rr++) {
        int r = rb * 16 + rr;
        int i = bi + r;
        if (i >= N_NODES) break;
        float4 a = si[r];
        float4 o;
        o.x = pdist(a, b0);
        o.y = pdist(a, b1);
        o.z = pdist(a, b2);
        o.w = pdist(a, b3);
        *(float4*)(out + (size_t)i * N_NODES + j0) = o;
    }
}

// ---------------- launch ----------------
extern "C" void kernel_launch(void* const* d_in, const int* in_sizes, int n_in,
                              void* d_out, int out_size)
{
    const float* x   = (const float*)d_in[0];
    const int*   ei  = (const int*)d_in[1];   // int32 (JAX x64-disabled downcast; confirmed R1/R2)
    const float* W_l = (const float*)d_in[2];
    const float* b_l = (const float*)d_in[3];
    const float* W_r = (const float*)d_in[4];
    const float* Wa  = (const float*)d_in[5];
    const float* ba  = (const float*)d_in[6];
    const float* W1  = (const float*)d_in[7];
    const float* b1  = (const float*)d_in[8];
    const float* W2  = (const float*)d_in[9];
    const float* b2  = (const float*)d_in[10];
    const float* W3  = (const float*)d_in[11];
    const float* b3  = (const float*)d_in[12];
    float* out = (float*)d_out;

    static int attr_done = 0;
    if (!attr_done) {
        cudaFuncSetAttribute(mlp_kernel,
                             cudaFuncAttributeMaxDynamicSharedMemorySize, MLP_SMEM);
        attr_done = 1;
    }

    const int MBLK = (N_NODES + 127) / 128;   // 79
    const int MBLK64 = (N_NODES + 63) / 64;   // 157

    // [0] big GEMM (Y, R) + fused edge-count band
    sage_gemm4_kernel<<<dim3(5, MBLK64), 256>>>(x, W_l, W_r, ei);
    // [1] prefix scan (+ re-zero counts)
    scan_kernel<<<1, 1024>>>();
    // [2] CSR scatter
    scatter_kernel<<<(N_EDGES + 255) / 256, 256>>>(ei);
    // [3] aggregation (ncu capture slot)
    aggr_kernel<<<(N_NODES * 32 + 255) / 256, 256>>>(b_l);
    // [4] fused MLP + final
    mlp_kernel<<<MBLK64, 256, MLP_SMEM>>>(Wa, ba, W1, b1, W2, b2, W3, b3);
    // [5] pairwise distances
    dist_kernel<<<dim3(MBLK, MBLK), 256>>>(out);

    (void)in_sizes; (void)n_in; (void)out_size;
}

// round 15
// speedup vs baseline: 1.2239x; 1.0160x over previous
#include <cuda_runtime.h>
#include <cstdint>
#include <cstddef>

#define N_NODES 10000
#define N_EDGES 160000
typedef unsigned long long ull;

// ---------------- scratch ----------------
__device__ float g_Y [N_NODES * 256];
__device__ float g_R [N_NODES * 256];
__device__ float g_H [N_NODES * 256];
__device__ float4 g_F [N_NODES];
__device__ int   g_cnt[N_NODES];          // zero-initialized by loader; re-zeroed in scan
__device__ int   g_off[N_NODES + 1];
__device__ int   g_cur[N_NODES];
__device__ int   g_csr[N_EDGES];

// ---------------- big fused GEMM + edge count band ----------------
__global__ __launch_bounds__(256, 3)
void sage_gemm4_kernel(const float* __restrict__ X,
                       const float* __restrict__ Wl, const float* __restrict__ Wr,
                       const int* __restrict__ ei)
{
    constexpr int BK = 16, ASTRIDE = 72;
    __shared__ float AsT[BK][ASTRIDE];
    __shared__ __align__(16) float Bs[BK][128];

    int tid = threadIdx.x;
    int bx = blockIdx.x;

    if (bx == 4) {   // edge-count band
        int e = blockIdx.y * 256 + tid;
        for (; e < N_EDGES; e += 40192)
            atomicAdd(&g_cnt[ei[N_EDGES + e]], 1);
        return;
    }

    int lane = tid & 31, wid = tid >> 5;
    int bm0 = blockIdx.y * 64;
    const float* B = (bx < 2) ? Wl : Wr;
    float* C = (bx < 2) ? g_Y : g_R;
    int bn0 = (bx & 1) * 128;

    int rA = tid >> 2, qA = tid & 3;
    int rB = tid >> 5, cB = tid & 31;
    int rowA = bm0 + rA;
    const float* pA = X + (size_t)rowA * 512 + qA * 4;
    const float* pB0 = B + (size_t)rB * 256 + bn0 + cB * 4;
    const float* pB1 = B + (size_t)(rB + 8) * 256 + bn0 + cB * 4;

    ull acc2[4][4];
#pragma unroll
    for (int i = 0; i < 4; i++)
#pragma unroll
        for (int j = 0; j < 4; j++) acc2[i][j] = 0ull;

    for (int c = 0; c < 32; c++) {
        int k0 = c * BK;
        float4 a = (rowA < N_NODES) ? *(const float4*)(pA + k0)
                                    : make_float4(0.f, 0.f, 0.f, 0.f);
        float4 b0 = *(const float4*)(pB0 + (size_t)k0 * 256);
        float4 b1 = *(const float4*)(pB1 + (size_t)k0 * 256);

        AsT[qA * 4 + 0][rA] = a.x;
        AsT[qA * 4 + 1][rA] = a.y;
        AsT[qA * 4 + 2][rA] = a.z;
        AsT[qA * 4 + 3][rA] = a.w;
        *(float4*)&Bs[rB][cB * 4]     = b0;
        *(float4*)&Bs[rB + 8][cB * 4] = b1;
        __syncthreads();

#pragma unroll
        for (int k = 0; k < BK; k++) {
            const ulonglong2* ap = (const ulonglong2*)&AsT[k][wid * 8];
            ulonglong2 a01 = ap[0], a23 = ap[1];
            ull av[4] = { a01.x, a01.y, a23.x, a23.y };
            float2 f0 = *(const float2*)&Bs[k][2 * lane];
            float2 f1 = *(const float2*)&Bs[k][2 * lane + 64];
            ull b00, b01, b10, b11;
            asm("mov.b64 %0, {%1, %1};" : "=l"(b00) : "f"(f0.x));
            asm("mov.b64 %0, {%1, %1};" : "=l"(b01) : "f"(f0.y));
            asm("mov.b64 %0, {%1, %1};" : "=l"(b10) : "f"(f1.x));
            asm("mov.b64 %0, {%1, %1};" : "=l"(b11) : "f"(f1.y));
#pragma unroll
            for (int i = 0; i < 4; i++) {
                asm("fma.rn.f32x2 %0, %1, %2, %0;" : "+l"(acc2[i][0]) : "l"(av[i]), "l"(b00));
                asm("fma.rn.f32x2 %0, %1, %2, %0;" : "+l"(acc2[i][1]) : "l"(av[i]), "l"(b01));
                asm("fma.rn.f32x2 %0, %1, %2, %0;" : "+l"(acc2[i][2]) : "l"(av[i]), "l"(b10));
                asm("fma.rn.f32x2 %0, %1, %2, %0;" : "+l"(acc2[i][3]) : "l"(av[i]), "l"(b11));
            }
        }
        __syncthreads();
    }

#pragma unroll
    for (int i = 0; i < 4; i++) {
#pragma unroll
        for (int p = 0; p < 2; p++) {
            int row = bm0 + wid * 8 + 2 * i + p;
            if (row >= N_NODES) continue;
#pragma unroll
            for (int jj = 0; jj < 2; jj++) {
                int col = bn0 + 2 * lane + 64 * jj;
                ull u0 = acc2[i][2 * jj], u1 = acc2[i][2 * jj + 1];
                float v0 = __uint_as_float(p ? (unsigned)(u0 >> 32) : (unsigned)u0);
                float v1 = __uint_as_float(p ? (unsigned)(u1 >> 32) : (unsigned)u1);
                *(float2*)(C + (size_t)row * 256 + col) = make_float2(v0, v1);
            }
        }
    }
}

// ---------------- scan (re-zeroes g_cnt) ----------------
__global__ void scan_kernel() {
    __shared__ int stage[10240];
    __shared__ int wsum[32];
    int t = threadIdx.x;
    int lane = t & 31, w = t >> 5;
#pragma unroll
    for (int i = 0; i < 10; i++) {
        int idx = t + i * 1024;
        stage[idx] = (idx < N_NODES) ? g_cnt[idx] : 0;
    }
    __syncthreads();
    int base = t * 10;
    int local[10];
    int s = 0;
#pragma unroll
    for (int i = 0; i < 10; i++) { local[i] = stage[base + i]; s += local[i]; }
    int v = s;
#pragma unroll
    for (int o = 1; o < 32; o <<= 1) {
        int u = __shfl_up_sync(0xFFFFFFFFu, v, o);
        if (lane >= o) v += u;
    }
    if (lane == 31) wsum[w] = v;
    __syncthreads();
    if (w == 0) {
        int x2 = wsum[lane];
#pragma unroll
        for (int o = 1; o < 32; o <<= 1) {
            int u = __shfl_up_sync(0xFFFFFFFFu, x2, o);
            if (lane >= o) x2 += u;
        }
        wsum[lane] = x2;
    }
    __syncthreads();
    int pre = v - s + (w > 0 ? wsum[w - 1] : 0);
#pragma unroll
    for (int i = 0; i < 10; i++) { stage[base + i] = pre; pre += local[i]; }
    if (t == 1023) g_off[N_NODES] = wsum[31];
    __syncthreads();
#pragma unroll
    for (int i = 0; i < 10; i++) {
        int idx = t + i * 1024;
        if (idx < N_NODES) {
            int p = stage[idx];
            g_off[idx] = p;
            g_cur[idx] = p;
            g_cnt[idx] = 0;
        }
    }
}

__global__ void scatter_kernel(const int* __restrict__ ei) {
    int e = blockIdx.x * blockDim.x + threadIdx.x;
    if (e < N_EDGES) {
        int s = ei[e];
        int d = ei[N_EDGES + e];
        int p = atomicAdd(&g_cur[d], 1);
        g_csr[p] = s;
    }
}

// ---------------- aggregation (2-edge unroll; identical fp add order) ----------------
__global__ void aggr_kernel(const float* __restrict__ b_l) {
    int warp = (blockIdx.x * blockDim.x + threadIdx.x) >> 5;
    int lane = threadIdx.x & 31;
    if (warp >= N_NODES) return;
    int s0 = g_off[warp], s1 = g_off[warp + 1];

    float4 a0 = make_float4(0.f, 0.f, 0.f, 0.f);
    float4 a1 = a0;
    const float4* Y4 = (const float4*)g_Y;
    int e = s0;
    for (; e + 1 < s1; e += 2) {
        int sa = g_csr[e];
        int sb = g_csr[e + 1];
        float4 va0 = __ldg(&Y4[(size_t)sa * 64 + lane]);
        float4 va1 = __ldg(&Y4[(size_t)sa * 64 + 32 + lane]);
        float4 vb0 = __ldg(&Y4[(size_t)sb * 64 + lane]);
        float4 vb1 = __ldg(&Y4[(size_t)sb * 64 + 32 + lane]);
        a0.x += va0.x; a0.y += va0.y; a0.z += va0.z; a0.w += va0.w;
        a1.x += va1.x; a1.y += va1.y; a1.z += va1.z; a1.w += va1.w;
        a0.x += vb0.x; a0.y += vb0.y; a0.z += vb0.z; a0.w += vb0.w;
        a1.x += vb1.x; a1.y += vb1.y; a1.z += vb1.z; a1.w += vb1.w;
    }
    if (e < s1) {
        int sa = g_csr[e];
        float4 v0 = __ldg(&Y4[(size_t)sa * 64 + lane]);
        float4 v1 = __ldg(&Y4[(size_t)sa * 64 + 32 + lane]);
        a0.x += v0.x; a0.y += v0.y; a0.z += v0.z; a0.w += v0.w;
        a1.x += v1.x; a1.y += v1.y; a1.z += v1.z; a1.w += v1.w;
    }
    int deg = s1 - s0;
    float inv = (deg > 0) ? 1.0f / (float)deg : 1.0f;

    const float4* R4 = (const float4*)g_R;
    const float4* BL = (const float4*)b_l;
    float4* H4 = (float4*)g_H;

    float4 r0 = R4[(size_t)warp * 64 + lane];
    float4 r1 = R4[(size_t)warp * 64 + 32 + lane];
    float4 bl0 = BL[lane];
    float4 bl1 = BL[lane + 32];

    float4 o0, o1;
    o0.x = fmaxf(a0.x * inv + bl0.x + r0.x, 0.f);
    o0.y = fmaxf(a0.y * inv + bl0.y + r0.y, 0.f);
    o0.z = fmaxf(a0.z * inv + bl0.z + r0.z, 0.f);
    o0.w = fmaxf(a0.w * inv + bl0.w + r0.w, 0.f);
    o1.x = fmaxf(a1.x * inv + bl1.x + r1.x, 0.f);
    o1.y = fmaxf(a1.y * inv + bl1.y + r1.y, 0.f);
    o1.z = fmaxf(a1.z * inv + bl1.z + r1.z, 0.f);
    o1.w = fmaxf(a1.w * inv + bl1.w + r1.w, 0.f);
    H4[(size_t)warp * 64 + lane] = o0;
    H4[(size_t)warp * 64 + 32 + lane] = o1;
}

// ---------------- fused MLP (256->128->64->32->3) + features ----------------
#define S2 66
#define SA 68
#define MLP_SMEM ((128 * S2 + 64 * S2 + 32 * S2 + 2048 + 16 * SA) * 4)

__global__ __launch_bounds__(256)
void mlp_kernel(const float* __restrict__ Wa, const float* __restrict__ ba,
                const float* __restrict__ W1, const float* __restrict__ b1,
                const float* __restrict__ W2, const float* __restrict__ b2,
                const float* __restrict__ W3, const float* __restrict__ b3)
{
    extern __shared__ __align__(16) float sm[];
    float* H2s = sm;
    float* H3s = H2s + 128 * S2;
    float* H4s = H3s + 64 * S2;
    float* Ws  = H4s + 32 * S2;
    float* Ast = Ws + 2048;

    int tid = threadIdx.x;
    int tx = tid & 15, ty = tid >> 4;
    int bm0 = blockIdx.x * 64;

    {   // layer 1
        ull acc[2][8];
#pragma unroll
        for (int i = 0; i < 2; i++)
#pragma unroll
            for (int j = 0; j < 8; j++) acc[i][j] = 0ull;

        int r = tid >> 2, q = tid & 3;
        int row = bm0 + r;
        for (int k0 = 0; k0 < 256; k0 += 16) {
            float4 v = make_float4(0.f, 0.f, 0.f, 0.f);
            if (row < N_NODES) v = *(const float4*)(g_H + (size_t)row * 256 + k0 + q * 4);
            Ast[(q * 4 + 0) * SA + r] = v.x;
            Ast[(q * 4 + 1) * SA + r] = v.y;
            Ast[(q * 4 + 2) * SA + r] = v.z;
            Ast[(q * 4 + 3) * SA + r] = v.w;
#pragma unroll
            for (int idx = tid; idx < 2048; idx += 256) {
                int rr = idx >> 7, cc = idx & 127;
                Ws[idx] = Wa[(size_t)(k0 + rr) * 128 + cc];
            }
            __syncthreads();
#pragma unroll
            for (int k = 0; k < 16; k++) {
                ull av0 = *(const ull*)&Ast[k * SA + ty * 4];
                ull av1 = *(const ull*)&Ast[k * SA + ty * 4 + 2];
#pragma unroll
                for (int j = 0; j < 4; j++) {
                    float2 f = *(const float2*)&Ws[k * 128 + 2 * tx + 32 * j];
                    ull bp0, bp1;
                    asm("mov.b64 %0, {%1, %1};" : "=l"(bp0) : "f"(f.x));
                    asm("mov.b64 %0, {%1, %1};" : "=l"(bp1) : "f"(f.y));
                    asm("fma.rn.f32x2 %0, %1, %2, %0;" : "+l"(acc[0][2 * j])     : "l"(av0), "l"(bp0));
                    asm("fma.rn.f32x2 %0, %1, %2, %0;" : "+l"(acc[1][2 * j])     : "l"(av1), "l"(bp0));
                    asm("fma.rn.f32x2 %0, %1, %2, %0;" : "+l"(acc[0][2 * j + 1]) : "l"(av0), "l"(bp1));
                    asm("fma.rn.f32x2 %0, %1, %2, %0;" : "+l"(acc[1][2 * j + 1]) : "l"(av1), "l"(bp1));
                }
            }
            __syncthreads();
        }
#pragma unroll
        for (int i = 0; i < 2; i++)
#pragma unroll
            for (int p = 0; p < 2; p++) {
                int rl = ty * 4 + 2 * i + p;
#pragma unroll
                for (int j = 0; j < 4; j++) {
                    int col = 2 * tx + 32 * j;
                    ull u0 = acc[i][2 * j], u1 = acc[i][2 * j + 1];
                    float v0 = __uint_as_float(p ? (unsigned)(u0 >> 32) : (unsigned)u0) + ba[col];
                    float v1 = __uint_as_float(p ? (unsigned)(u1 >> 32) : (unsigned)u1) + ba[col + 1];
                    H2s[col * S2 + rl]       = fmaxf(v0, 0.f);
                    H2s[(col + 1) * S2 + rl] = fmaxf(v1, 0.f);
                }
            }
        __syncthreads();
    }

    {   // layer 2
        ull acc[2][4];
#pragma unroll
        for (int i = 0; i < 2; i++)
#pragma unroll
            for (int j = 0; j < 4; j++) acc[i][j] = 0ull;

        for (int k0 = 0; k0 < 128; k0 += 16) {
#pragma unroll
            for (int idx = tid; idx < 1024; idx += 256) {
                int rr = idx >> 6, cc = idx & 63;
                Ws[idx] = W1[(size_t)(k0 + rr) * 64 + cc];
            }
            __syncthreads();
#pragma unroll
            for (int k = 0; k < 16; k++) {
                ull av0 = *(const ull*)&H2s[(k0 + k) * S2 + ty * 4];
                ull av1 = *(const ull*)&H2s[(k0 + k) * S2 + ty * 4 + 2];
#pragma unroll
                for (int j = 0; j < 2; j++) {
                    float2 f = *(const float2*)&Ws[k * 64 + 2 * tx + 32 * j];
                    ull bp0, bp1;
                    asm("mov.b64 %0, {%1, %1};" : "=l"(bp0) : "f"(f.x));
                    asm("mov.b64 %0, {%1, %1};" : "=l"(bp1) : "f"(f.y));
                    asm("fma.rn.f32x2 %0, %1, %2, %0;" : "+l"(acc[0][2 * j])     : "l"(av0), "l"(bp0));
                    asm("fma.rn.f32x2 %0, %1, %2, %0;" : "+l"(acc[1][2 * j])     : "l"(av1), "l"(bp0));
                    asm("fma.rn.f32x2 %0, %1, %2, %0;" : "+l"(acc[0][2 * j + 1]) : "l"(av0), "l"(bp1));
                    asm("fma.rn.f32x2 %0, %1, %2, %0;" : "+l"(acc[1][2 * j + 1]) : "l"(av1), "l"(bp1));
                }
            }
            __syncthreads();
        }
#pragma unroll
        for (int i = 0; i < 2; i++)
#pragma unroll
            for (int p = 0; p < 2; p++) {
                int rl = ty * 4 + 2 * i + p;
#pragma unroll
                for (int j = 0; j < 2; j++) {
                    int col = 2 * tx + 32 * j;
                    ull u0 = acc[i][2 * j], u1 = acc[i][2 * j + 1];
                    float v0 = __uint_as_float(p ? (unsigned)(u0 >> 32) : (unsigned)u0) + b1[col];
                    float v1 = __uint_as_float(p ? (unsigned)(u1 >> 32) : (unsigned)u1) + b1[col + 1];
                    H3s[col * S2 + rl]       = fmaxf(v0, 0.f);
                    H3s[(col + 1) * S2 + rl] = fmaxf(v1, 0.f);
                }
            }
        __syncthreads();
    }

    {   // layer 3
        ull acc[2][2];
#pragma unroll
        for (int i = 0; i < 2; i++)
#pragma unroll
            for (int j = 0; j < 2; j++) acc[i][j] = 0ull;

        for (int k0 = 0; k0 < 64; k0 += 16) {
#pragma unroll
            for (int idx = tid; idx < 512; idx += 256) {
                int rr = idx >> 5, cc = idx & 31;
                Ws[idx] = W2[(size_t)(k0 + rr) * 32 + cc];
            }
            __syncthreads();
#pragma unroll
            for (int k = 0; k < 16; k++) {
                ull av0 = *(const ull*)&H3s[(k0 + k) * S2 + ty * 4];
                ull av1 = *(const ull*)&H3s[(k0 + k) * S2 + ty * 4 + 2];
                float2 f = *(const float2*)&Ws[k * 32 + 2 * tx];
                ull bp0, bp1;
                asm("mov.b64 %0, {%1, %1};" : "=l"(bp0) : "f"(f.x));
                asm("mov.b64 %0, {%1, %1};" : "=l"(bp1) : "f"(f.y));
                asm("fma.rn.f32x2 %0, %1, %2, %0;" : "+l"(acc[0][0]) : "l"(av0), "l"(bp0));
                asm("fma.rn.f32x2 %0, %1, %2, %0;" : "+l"(acc[1][0]) : "l"(av1), "l"(bp0));
                asm("fma.rn.f32x2 %0, %1, %2, %0;" : "+l"(acc[0][1]) : "l"(av0), "l"(bp1));
                asm("fma.rn.f32x2 %0, %1, %2, %0;" : "+l"(acc[1][1]) : "l"(av1), "l"(bp1));
            }
            __syncthreads();
        }
#pragma unroll
        for (int i = 0; i < 2; i++)
#pragma unroll
            for (int p = 0; p < 2; p++) {
                int rl = ty * 4 + 2 * i + p;
                int col = 2 * tx;
                ull u0 = acc[i][0], u1 = acc[i][1];
                float v0 = __uint_as_float(p ? (unsigned)(u0 >> 32) : (unsigned)u0) + b2[col];
                float v1 = __uint_as_float(p ? (unsigned)(u1 >> 32) : (unsigned)u1) + b2[col + 1];
                H4s[col * S2 + rl]       = fmaxf(v0, 0.f);
                H4s[(col + 1) * S2 + rl] = fmaxf(v1, 0.f);
            }
        __syncthreads();
    }

    if (tid < 64) {
        int grow = bm0 + tid;
        if (grow < N_NODES) {
            float a0 = b3[0], a1 = b3[1], a2 = b3[2];
#pragma unroll
            for (int k = 0; k < 32; k++) {
                float hv = H4s[k * S2 + tid];
                a0 += hv * W3[k * 3 + 0];
                a1 += hv * W3[k * 3 + 1];
                a2 += hv * W3[k * 3 + 2];
            }
            g_F[grow] = make_float4(a0, a1, a2, a0 * a0 + a1 * a1 + a2 * a2);
        }
    }
}

// ---------------- pairwise L2 (streaming stores) ----------------
__device__ __forceinline__ float pdist(float4 a, float4 b) {
    float d2 = a.w + b.w - 2.0f * (a.x * b.x + a.y * b.y + a.z * b.z);
    if (d2 <= 0.f) return 0.f;
    float r;
    asm("sqrt.approx.f32 %0, %1;" : "=f"(r) : "f"(d2));
    return r;
}

__global__ __launch_bounds__(256)
void dist_kernel(float* __restrict__ out) {
    __shared__ float4 si[128], sj[128];
    int bi = blockIdx.y * 128, bj = blockIdx.x * 128;
    int t = threadIdx.x;
    if (t < 128) {
        int i = bi + t;
        si[t] = (i < N_NODES) ? g_F[i] : make_float4(0.f, 0.f, 0.f, 0.f);
    } else {
        int j = bj + t - 128;
        sj[t - 128] = (j < N_NODES) ? g_F[j] : make_float4(0.f, 0.f, 0.f, 0.f);
    }
    __syncthreads();

    int c4 = t & 31;
    int rb = t >> 5;
    int j0 = bj + c4 * 4;
    if (j0 >= N_NODES) return;

    float4 b0 = sj[c4 * 4 + 0];
    float4 b1 = sj[c4 * 4 + 1];
    float4 b2 = sj[c4 * 4 + 2];
    float4 b3 = sj[c4 * 4 + 3];

#pragma unroll 4
    for (int rr = 0; rr < 16; rr++) {
        int r = rb * 16 + rr;
        int i = bi + r;
        if (i >= N_NODES) break;
        float4 a = si[r];
        float4 o;
        o.x = pdist(a, b0);
        o.y = pdist(a, b1);
        o.z = pdist(a, b2);
        o.w = pdist(a, b3);
        float* p = out + (size_t)i * N_NODES + j0;
        asm volatile("st.global.cs.v4.f32 [%0], {%1,%2,%3,%4};"
                     :: "l"(p), "f"(o.x), "f"(o.y), "f"(o.z), "f"(o.w) : "memory");
    }
}

// ---------------- launch ----------------
extern "C" void kernel_launch(void* const* d_in, const int* in_sizes, int n_in,
                              void* d_out, int out_size)
{
    const float* x   = (const float*)d_in[0];
    const int*   ei  = (const int*)d_in[1];
    const float* W_l = (const float*)d_in[2];
    const float* b_l = (const float*)d_in[3];
    const float* W_r = (const float*)d_in[4];
    const float* Wa  = (const float*)d_in[5];
    const float* ba  = (const float*)d_in[6];
    const float* W1  = (const float*)d_in[7];
    const float* b1  = (const float*)d_in[8];
    const float* W2  = (const float*)d_in[9];
    const float* b2  = (const float*)d_in[10];
    const float* W3  = (const float*)d_in[11];
    const float* b3  = (const float*)d_in[12];
    float* out = (float*)d_out;

    static int attr_done = 0;
    if (!attr_done) {
        cudaFuncSetAttribute(mlp_kernel,
                             cudaFuncAttributeMaxDynamicSharedMemorySize, MLP_SMEM);
        attr_done = 1;
    }

    const int MBLK = (N_NODES + 127) / 128;   // 79
    const int MBLK64 = (N_NODES + 63) / 64;   // 157

    sage_gemm4_kernel<<<dim3(5, MBLK64), 256>>>(x, W_l, W_r, ei);
    scan_kernel<<<1, 1024>>>();
    scatter_kernel<<<(N_EDGES + 255) / 256, 256>>>(ei);
    aggr_kernel<<<(N_NODES * 32 + 255) / 256, 256>>>(b_l);
    mlp_kernel<<<MBLK64, 256, MLP_SMEM>>>(Wa, ba, W1, b1, W2, b2, W3, b3);
    dist_kernel<<<dim3(MBLK, MBLK), 256>>>(out);

    (void)in_sizes; (void)n_in; (void)out_size;
}

// round 16
// speedup vs baseline: 1.2429x; 1.0155x over previous
#include <cuda_runtime.h>
#include <cstdint>
#include <cstddef>

#define N_NODES 10000
#define N_EDGES 160000
typedef unsigned long long ull;

// ---------------- scratch ----------------
__device__ float g_Y [N_NODES * 256];
__device__ float g_R [N_NODES * 256];
__device__ float g_H [N_NODES * 256];
__device__ float4 g_F [N_NODES];
__device__ int   g_cnt[N_NODES];          // zero-initialized by loader; re-zeroed in scan
__device__ int   g_off[N_NODES + 1];
__device__ int   g_cur[N_NODES];
__device__ int   g_csr[N_EDGES];

// ---------------- big fused GEMM (R11 config) ----------------
__global__ __launch_bounds__(256, 3)
void sage_gemm4_kernel(const float* __restrict__ X,
                       const float* __restrict__ Wl, const float* __restrict__ Wr)
{
    constexpr int BK = 16, ASTRIDE = 72;
    __shared__ float AsT[BK][ASTRIDE];
    __shared__ __align__(16) float Bs[BK][128];

    int tid = threadIdx.x;
    int bx = blockIdx.x;
    int lane = tid & 31, wid = tid >> 5;
    int bm0 = blockIdx.y * 64;
    const float* B = (bx < 2) ? Wl : Wr;
    float* C = (bx < 2) ? g_Y : g_R;
    int bn0 = (bx & 1) * 128;

    int rA = tid >> 2, qA = tid & 3;
    int rB = tid >> 5, cB = tid & 31;
    int rowA = bm0 + rA;
    const float* pA = X + (size_t)rowA * 512 + qA * 4;
    const float* pB0 = B + (size_t)rB * 256 + bn0 + cB * 4;
    const float* pB1 = B + (size_t)(rB + 8) * 256 + bn0 + cB * 4;

    ull acc2[4][4];
#pragma unroll
    for (int i = 0; i < 4; i++)
#pragma unroll
        for (int j = 0; j < 4; j++) acc2[i][j] = 0ull;

    for (int c = 0; c < 32; c++) {
        int k0 = c * BK;
        float4 a = (rowA < N_NODES) ? *(const float4*)(pA + k0)
                                    : make_float4(0.f, 0.f, 0.f, 0.f);
        float4 b0 = *(const float4*)(pB0 + (size_t)k0 * 256);
        float4 b1 = *(const float4*)(pB1 + (size_t)k0 * 256);

        AsT[qA * 4 + 0][rA] = a.x;
        AsT[qA * 4 + 1][rA] = a.y;
        AsT[qA * 4 + 2][rA] = a.z;
        AsT[qA * 4 + 3][rA] = a.w;
        *(float4*)&Bs[rB][cB * 4]     = b0;
        *(float4*)&Bs[rB + 8][cB * 4] = b1;
        __syncthreads();

#pragma unroll
        for (int k = 0; k < BK; k++) {
            const ulonglong2* ap = (const ulonglong2*)&AsT[k][wid * 8];
            ulonglong2 a01 = ap[0], a23 = ap[1];
            ull av[4] = { a01.x, a01.y, a23.x, a23.y };
            float2 f0 = *(const float2*)&Bs[k][2 * lane];
            float2 f1 = *(const float2*)&Bs[k][2 * lane + 64];
            ull b00, b01, b10, b11;
            asm("mov.b64 %0, {%1, %1};" : "=l"(b00) : "f"(f0.x));
            asm("mov.b64 %0, {%1, %1};" : "=l"(b01) : "f"(f0.y));
            asm("mov.b64 %0, {%1, %1};" : "=l"(b10) : "f"(f1.x));
            asm("mov.b64 %0, {%1, %1};" : "=l"(b11) : "f"(f1.y));
#pragma unroll
            for (int i = 0; i < 4; i++) {
                asm("fma.rn.f32x2 %0, %1, %2, %0;" : "+l"(acc2[i][0]) : "l"(av[i]), "l"(b00));
                asm("fma.rn.f32x2 %0, %1, %2, %0;" : "+l"(acc2[i][1]) : "l"(av[i]), "l"(b01));
                asm("fma.rn.f32x2 %0, %1, %2, %0;" : "+l"(acc2[i][2]) : "l"(av[i]), "l"(b10));
                asm("fma.rn.f32x2 %0, %1, %2, %0;" : "+l"(acc2[i][3]) : "l"(av[i]), "l"(b11));
            }
        }
        __syncthreads();
    }

#pragma unroll
    for (int i = 0; i < 4; i++) {
#pragma unroll
        for (int p = 0; p < 2; p++) {
            int row = bm0 + wid * 8 + 2 * i + p;
            if (row >= N_NODES) continue;
#pragma unroll
            for (int jj = 0; jj < 2; jj++) {
                int col = bn0 + 2 * lane + 64 * jj;
                ull u0 = acc2[i][2 * jj], u1 = acc2[i][2 * jj + 1];
                float v0 = __uint_as_float(p ? (unsigned)(u0 >> 32) : (unsigned)u0);
                float v1 = __uint_as_float(p ? (unsigned)(u1 >> 32) : (unsigned)u1);
                *(float2*)(C + (size_t)row * 256 + col) = make_float2(v0, v1);
            }
        }
    }
}

// ---------------- CSR chain (side stream) ----------------
__global__ void count_kernel(const int* __restrict__ ei) {
    int e = blockIdx.x * blockDim.x + threadIdx.x;
    if (e < N_EDGES) atomicAdd(&g_cnt[ei[N_EDGES + e]], 1);
}

__global__ void scan_kernel() {
    __shared__ int stage[10240];
    __shared__ int wsum[32];
    int t = threadIdx.x;
    int lane = t & 31, w = t >> 5;
#pragma unroll
    for (int i = 0; i < 10; i++) {
        int idx = t + i * 1024;
        stage[idx] = (idx < N_NODES) ? g_cnt[idx] : 0;
    }
    __syncthreads();
    int base = t * 10;
    int local[10];
    int s = 0;
#pragma unroll
    for (int i = 0; i < 10; i++) { local[i] = stage[base + i]; s += local[i]; }
    int v = s;
#pragma unroll
    for (int o = 1; o < 32; o <<= 1) {
        int u = __shfl_up_sync(0xFFFFFFFFu, v, o);
        if (lane >= o) v += u;
    }
    if (lane == 31) wsum[w] = v;
    __syncthreads();
    if (w == 0) {
        int x2 = wsum[lane];
#pragma unroll
        for (int o = 1; o < 32; o <<= 1) {
            int u = __shfl_up_sync(0xFFFFFFFFu, x2, o);
            if (lane >= o) x2 += u;
        }
        wsum[lane] = x2;
    }
    __syncthreads();
    int pre = v - s + (w > 0 ? wsum[w - 1] : 0);
#pragma unroll
    for (int i = 0; i < 10; i++) { stage[base + i] = pre; pre += local[i]; }
    if (t == 1023) g_off[N_NODES] = wsum[31];
    __syncthreads();
#pragma unroll
    for (int i = 0; i < 10; i++) {
        int idx = t + i * 1024;
        if (idx < N_NODES) {
            int p = stage[idx];
            g_off[idx] = p;
            g_cur[idx] = p;
            g_cnt[idx] = 0;
        }
    }
}

__global__ void scatter_kernel(const int* __restrict__ ei) {
    int e = blockIdx.x * blockDim.x + threadIdx.x;
    if (e < N_EDGES) {
        int s = ei[e];
        int d = ei[N_EDGES + e];
        int p = atomicAdd(&g_cur[d], 1);
        g_csr[p] = s;
    }
}

// ---------------- aggregation: 2 warps per node, 4-edge unroll ----------------
__global__ void aggr_kernel(const float* __restrict__ b_l) {
    int gw = (blockIdx.x * blockDim.x + threadIdx.x) >> 5;
    int node = gw >> 1;
    int half = gw & 1;
    int lane = threadIdx.x & 31;
    if (node >= N_NODES) return;
    int s0 = g_off[node], s1 = g_off[node + 1];

    int fi = half * 32 + lane;        // float4 index within row (0..63)
    float4 a = make_float4(0.f, 0.f, 0.f, 0.f);
    const float4* Y4 = (const float4*)g_Y;
    int e = s0;
    for (; e + 3 < s1; e += 4) {
        int sa = g_csr[e], sb = g_csr[e + 1], sc = g_csr[e + 2], sd = g_csr[e + 3];
        float4 va = __ldg(&Y4[(size_t)sa * 64 + fi]);
        float4 vb = __ldg(&Y4[(size_t)sb * 64 + fi]);
        float4 vc = __ldg(&Y4[(size_t)sc * 64 + fi]);
        float4 vd = __ldg(&Y4[(size_t)sd * 64 + fi]);
        a.x += va.x; a.y += va.y; a.z += va.z; a.w += va.w;
        a.x += vb.x; a.y += vb.y; a.z += vb.z; a.w += vb.w;
        a.x += vc.x; a.y += vc.y; a.z += vc.z; a.w += vc.w;
        a.x += vd.x; a.y += vd.y; a.z += vd.z; a.w += vd.w;
    }
    for (; e < s1; e++) {
        int sa = g_csr[e];
        float4 v = __ldg(&Y4[(size_t)sa * 64 + fi]);
        a.x += v.x; a.y += v.y; a.z += v.z; a.w += v.w;
    }
    int deg = s1 - s0;
    float inv = (deg > 0) ? 1.0f / (float)deg : 1.0f;

    const float4* R4 = (const float4*)g_R;
    const float4* BL = (const float4*)b_l;
    float4* H4 = (float4*)g_H;

    float4 r = R4[(size_t)node * 64 + fi];
    float4 bl = BL[fi];
    float4 o;
    o.x = fmaxf(a.x * inv + bl.x + r.x, 0.f);
    o.y = fmaxf(a.y * inv + bl.y + r.y, 0.f);
    o.z = fmaxf(a.z * inv + bl.z + r.z, 0.f);
    o.w = fmaxf(a.w * inv + bl.w + r.w, 0.f);
    H4[(size_t)node * 64 + fi] = o;
}

// ---------------- fused MLP (256->128->64->32->3) + features ----------------
#define S2 66
#define SA 68
#define MLP_SMEM ((128 * S2 + 64 * S2 + 32 * S2 + 2048 + 16 * SA) * 4)

__global__ __launch_bounds__(256)
void mlp_kernel(const float* __restrict__ Wa, const float* __restrict__ ba,
                const float* __restrict__ W1, const float* __restrict__ b1,
                const float* __restrict__ W2, const float* __restrict__ b2,
                const float* __restrict__ W3, const float* __restrict__ b3)
{
    extern __shared__ __align__(16) float sm[];
    float* H2s = sm;
    float* H3s = H2s + 128 * S2;
    float* H4s = H3s + 64 * S2;
    float* Ws  = H4s + 32 * S2;
    float* Ast = Ws + 2048;

    int tid = threadIdx.x;
    int tx = tid & 15, ty = tid >> 4;
    int bm0 = blockIdx.x * 64;

    {   // layer 1
        ull acc[2][8];
#pragma unroll
        for (int i = 0; i < 2; i++)
#pragma unroll
            for (int j = 0; j < 8; j++) acc[i][j] = 0ull;

        int r = tid >> 2, q = tid & 3;
        int row = bm0 + r;
        for (int k0 = 0; k0 < 256; k0 += 16) {
            float4 v = make_float4(0.f, 0.f, 0.f, 0.f);
            if (row < N_NODES) v = *(const float4*)(g_H + (size_t)row * 256 + k0 + q * 4);
            Ast[(q * 4 + 0) * SA + r] = v.x;
            Ast[(q * 4 + 1) * SA + r] = v.y;
            Ast[(q * 4 + 2) * SA + r] = v.z;
            Ast[(q * 4 + 3) * SA + r] = v.w;
#pragma unroll
            for (int idx = tid; idx < 2048; idx += 256) {
                int rr = idx >> 7, cc = idx & 127;
                Ws[idx] = Wa[(size_t)(k0 + rr) * 128 + cc];
            }
            __syncthreads();
#pragma unroll
            for (int k = 0; k < 16; k++) {
                ull av0 = *(const ull*)&Ast[k * SA + ty * 4];
                ull av1 = *(const ull*)&Ast[k * SA + ty * 4 + 2];
#pragma unroll
                for (int j = 0; j < 4; j++) {
                    float2 f = *(const float2*)&Ws[k * 128 + 2 * tx + 32 * j];
                    ull bp0, bp1;
                    asm("mov.b64 %0, {%1, %1};" : "=l"(bp0) : "f"(f.x));
                    asm("mov.b64 %0, {%1, %1};" : "=l"(bp1) : "f"(f.y));
                    asm("fma.rn.f32x2 %0, %1, %2, %0;" : "+l"(acc[0][2 * j])     : "l"(av0), "l"(bp0));
                    asm("fma.rn.f32x2 %0, %1, %2, %0;" : "+l"(acc[1][2 * j])     : "l"(av1), "l"(bp0));
                    asm("fma.rn.f32x2 %0, %1, %2, %0;" : "+l"(acc[0][2 * j + 1]) : "l"(av0), "l"(bp1));
                    asm("fma.rn.f32x2 %0, %1, %2, %0;" : "+l"(acc[1][2 * j + 1]) : "l"(av1), "l"(bp1));
                }
            }
            __syncthreads();
        }
#pragma unroll
        for (int i = 0; i < 2; i++)
#pragma unroll
            for (int p = 0; p < 2; p++) {
                int rl = ty * 4 + 2 * i + p;
#pragma unroll
                for (int j = 0; j < 4; j++) {
                    int col = 2 * tx + 32 * j;
                    ull u0 = acc[i][2 * j], u1 = acc[i][2 * j + 1];
                    float v0 = __uint_as_float(p ? (unsigned)(u0 >> 32) : (unsigned)u0) + ba[col];
                    float v1 = __uint_as_float(p ? (unsigned)(u1 >> 32) : (unsigned)u1) + ba[col + 1];
                    H2s[col * S2 + rl]       = fmaxf(v0, 0.f);
                    H2s[(col + 1) * S2 + rl] = fmaxf(v1, 0.f);
                }
            }
        __syncthreads();
    }

    {   // layer 2
        ull acc[2][4];
#pragma unroll
        for (int i = 0; i < 2; i++)
#pragma unroll
            for (int j = 0; j < 4; j++) acc[i][j] = 0ull;

        for (int k0 = 0; k0 < 128; k0 += 16) {
#pragma unroll
            for (int idx = tid; idx < 1024; idx += 256) {
                int rr = idx >> 6, cc = idx & 63;
                Ws[idx] = W1[(size_t)(k0 + rr) * 64 + cc];
            }
            __syncthreads();
#pragma unroll
            for (int k = 0; k < 16; k++) {
                ull av0 = *(const ull*)&H2s[(k0 + k) * S2 + ty * 4];
                ull av1 = *(const ull*)&H2s[(k0 + k) * S2 + ty * 4 + 2];
#pragma unroll
                for (int j = 0; j < 2; j++) {
                    float2 f = *(const float2*)&Ws[k * 64 + 2 * tx + 32 * j];
                    ull bp0, bp1;
                    asm("mov.b64 %0, {%1, %1};" : "=l"(bp0) : "f"(f.x));
                    asm("mov.b64 %0, {%1, %1};" : "=l"(bp1) : "f"(f.y));
                    asm("fma.rn.f32x2 %0, %1, %2, %0;" : "+l"(acc[0][2 * j])     : "l"(av0), "l"(bp0));
                    asm("fma.rn.f32x2 %0, %1, %2, %0;" : "+l"(acc[1][2 * j])     : "l"(av1), "l"(bp0));
                    asm("fma.rn.f32x2 %0, %1, %2, %0;" : "+l"(acc[0][2 * j + 1]) : "l"(av0), "l"(bp1));
                    asm("fma.rn.f32x2 %0, %1, %2, %0;" : "+l"(acc[1][2 * j + 1]) : "l"(av1), "l"(bp1));
                }
            }
            __syncthreads();
        }
#pragma unroll
        for (int i = 0; i < 2; i++)
#pragma unroll
            for (int p = 0; p < 2; p++) {
                int rl = ty * 4 + 2 * i + p;
#pragma unroll
                for (int j = 0; j < 2; j++) {
                    int col = 2 * tx + 32 * j;
                    ull u0 = acc[i][2 * j], u1 = acc[i][2 * j + 1];
                    float v0 = __uint_as_float(p ? (unsigned)(u0 >> 32) : (unsigned)u0) + b1[col];
                    float v1 = __uint_as_float(p ? (unsigned)(u1 >> 32) : (unsigned)u1) + b1[col + 1];
                    H3s[col * S2 + rl]       = fmaxf(v0, 0.f);
                    H3s[(col + 1) * S2 + rl] = fmaxf(v1, 0.f);
                }
            }
        __syncthreads();
    }

    {   // layer 3
        ull acc[2][2];
#pragma unroll
        for (int i = 0; i < 2; i++)
#pragma unroll
            for (int j = 0; j < 2; j++) acc[i][j] = 0ull;

        for (int k0 = 0; k0 < 64; k0 += 16) {
#pragma unroll
            for (int idx = tid; idx < 512; idx += 256) {
                int rr = idx >> 5, cc = idx & 31;
                Ws[idx] = W2[(size_t)(k0 + rr) * 32 + cc];
            }
            __syncthreads();
#pragma unroll
            for (int k = 0; k < 16; k++) {
                ull av0 = *(const ull*)&H3s[(k0 + k) * S2 + ty * 4];
                ull av1 = *(const ull*)&H3s[(k0 + k) * S2 + ty * 4 + 2];
                float2 f = *(const float2*)&Ws[k * 32 + 2 * tx];
                ull bp0, bp1;
                asm("mov.b64 %0, {%1, %1};" : "=l"(bp0) : "f"(f.x));
                asm("mov.b64 %0, {%1, %1};" : "=l"(bp1) : "f"(f.y));
                asm("fma.rn.f32x2 %0, %1, %2, %0;" : "+l"(acc[0][0]) : "l"(av0), "l"(bp0));
                asm("fma.rn.f32x2 %0, %1, %2, %0;" : "+l"(acc[1][0]) : "l"(av1), "l"(bp0));
                asm("fma.rn.f32x2 %0, %1, %2, %0;" : "+l"(acc[0][1]) : "l"(av0), "l"(bp1));
                asm("fma.rn.f32x2 %0, %1, %2, %0;" : "+l"(acc[1][1]) : "l"(av1), "l"(bp1));
            }
            __syncthreads();
        }
#pragma unroll
        for (int i = 0; i < 2; i++)
#pragma unroll
            for (int p = 0; p < 2; p++) {
                int rl = ty * 4 + 2 * i + p;
                int col = 2 * tx;
                ull u0 = acc[i][0], u1 = acc[i][1];
                float v0 = __uint_as_float(p ? (unsigned)(u0 >> 32) : (unsigned)u0) + b2[col];
                float v1 = __uint_as_float(p ? (unsigned)(u1 >> 32) : (unsigned)u1) + b2[col + 1];
                H4s[col * S2 + rl]       = fmaxf(v0, 0.f);
                H4s[(col + 1) * S2 + rl] = fmaxf(v1, 0.f);
            }
        __syncthreads();
    }

    if (tid < 64) {
        int grow = bm0 + tid;
        if (grow < N_NODES) {
            float a0 = b3[0], a1 = b3[1], a2 = b3[2];
#pragma unroll
            for (int k = 0; k < 32; k++) {
                float hv = H4s[k * S2 + tid];
                a0 += hv * W3[k * 3 + 0];
                a1 += hv * W3[k * 3 + 1];
                a2 += hv * W3[k * 3 + 2];
            }
            g_F[grow] = make_float4(a0, a1, a2, a0 * a0 + a1 * a1 + a2 * a2);
        }
    }
}

// ---------------- pairwise L2 (streaming stores) ----------------
__device__ __forceinline__ float pdist(float4 a, float4 b) {
    float d2 = a.w + b.w - 2.0f * (a.x * b.x + a.y * b.y + a.z * b.z);
    if (d2 <= 0.f) return 0.f;
    float r;
    asm("sqrt.approx.f32 %0, %1;" : "=f"(r) : "f"(d2));
    return r;
}

__global__ __launch_bounds__(256)
void dist_kernel(float* __restrict__ out) {
    __shared__ float4 si[128], sj[128];
    int bi = blockIdx.y * 128, bj = blockIdx.x * 128;
    int t = threadIdx.x;
    if (t < 128) {
        int i = bi + t;
        si[t] = (i < N_NODES) ? g_F[i] : make_float4(0.f, 0.f, 0.f, 0.f);
    } else {
        int j = bj + t - 128;
        sj[t - 128] = (j < N_NODES) ? g_F[j] : make_float4(0.f, 0.f, 0.f, 0.f);
    }
    __syncthreads();

    int c4 = t & 31;
    int rb = t >> 5;
    int j0 = bj + c4 * 4;
    if (j0 >= N_NODES) return;

    float4 b0 = sj[c4 * 4 + 0];
    float4 b1 = sj[c4 * 4 + 1];
    float4 b2 = sj[c4 * 4 + 2];
    float4 b3 = sj[c4 * 4 + 3];

#pragma unroll 4
    for (int rr = 0; rr < 16; rr++) {
        int r = rb * 16 + rr;
        int i = bi + r;
        if (i >= N_NODES) break;
        float4 a = si[r];
        float4 o;
        o.x = pdist(a, b0);
        o.y = pdist(a, b1);
        o.z = pdist(a, b2);
        o.w = pdist(a, b3);
        float* p = out + (size_t)i * N_NODES + j0;
        asm volatile("st.global.cs.v4.f32 [%0], {%1,%2,%3,%4};"
                     :: "l"(p), "f"(o.x), "f"(o.y), "f"(o.z), "f"(o.w) : "memory");
    }
}

// ---------------- launch ----------------
extern "C" void kernel_launch(void* const* d_in, const int* in_sizes, int n_in,
                              void* d_out, int out_size)
{
    const float* x   = (const float*)d_in[0];
    const int*   ei  = (const int*)d_in[1];
    const float* W_l = (const float*)d_in[2];
    const float* b_l = (const float*)d_in[3];
    const float* W_r = (const float*)d_in[4];
    const float* Wa  = (const float*)d_in[5];
    const float* ba  = (const float*)d_in[6];
    const float* W1  = (const float*)d_in[7];
    const float* b1  = (const float*)d_in[8];
    const float* W2  = (const float*)d_in[9];
    const float* b2  = (const float*)d_in[10];
    const float* W3  = (const float*)d_in[11];
    const float* b3  = (const float*)d_in[12];
    float* out = (float*)d_out;

    static cudaStream_t s2;
    static cudaEvent_t ev0, ev1;
    static int init_done = 0;
    if (!init_done) {
        cudaStreamCreateWithFlags(&s2, cudaStreamNonBlocking);
        cudaEventCreateWithFlags(&ev0, cudaEventDisableTiming);
        cudaEventCreateWithFlags(&ev1, cudaEventDisableTiming);
        cudaFuncSetAttribute(mlp_kernel,
                             cudaFuncAttributeMaxDynamicSharedMemorySize, MLP_SMEM);
        init_done = 1;
    }

    const int MBLK = (N_NODES + 127) / 128;   // 79
    const int MBLK64 = (N_NODES + 63) / 64;   // 157

    // fork: CSR chain on side stream, GEMM on main stream
    cudaEventRecord(ev0, 0);
    cudaStreamWaitEvent(s2, ev0, 0);
    count_kernel<<<(N_EDGES + 255) / 256, 256, 0, s2>>>(ei);
    scan_kernel<<<1, 1024, 0, s2>>>();
    scatter_kernel<<<(N_EDGES + 255) / 256, 256, 0, s2>>>(ei);
    cudaEventRecord(ev1, s2);

    sage_gemm4_kernel<<<dim3(4, MBLK64), 256>>>(x, W_l, W_r);

    // join, then rest of the pipeline
    cudaStreamWaitEvent(0, ev1, 0);
    aggr_kernel<<<(N_NODES * 2 * 32 + 255) / 256, 256>>>(b_l);
    mlp_kernel<<<MBLK64, 256, MLP_SMEM>>>(Wa, ba, W1, b1, W2, b2, W3, b3);
    dist_kernel<<<dim3(MBLK, MBLK), 256>>>(out);

    (void)in_sizes; (void)n_in; (void)out_size;
}